// round 2
// baseline (speedup 1.0000x reference)
#include <cuda_runtime.h>
#include <cuda_bf16.h>
#include <cstdint>

// Problem shapes (fixed by dataset reference setup_inputs)
#define BB   8
#define LL   8192
#define DIN  256
#define DH   512
#define DOUT 256
#define CHK  1024
#define NCHK (LL / CHK)

// ---------------------------------------------------------------------------
// Scratch (device globals; no allocation allowed)
// ---------------------------------------------------------------------------
__device__ float g_w0c[BB * DH * DIN];
__device__ float g_w0m[BB * DH * DIN];
__device__ float g_w2c[BB * DH * DIN];
__device__ float g_w2m[BB * DH * DIN];
__device__ float g_w1c[BB * DOUT * DH];
__device__ float g_w1m[BB * DOUT * DH];
__device__ float g_w0n[BB * DH];
__device__ float g_w1n[BB * DOUT];
__device__ float g_w2n[BB * DH];
__device__ float g_G [BB * CHK * DH];   // gate_before_act  -> dgba*lr0
__device__ float g_HB[BB * CHK * DH];   // hidden_before_mul-> dhbm*lr2
__device__ float g_D [BB * CHK * DH];   // dhidden          -> hidden*lr1
__device__ float g_U [BB * CHK * DH];   // silu(g)*h for the q path

__device__ __forceinline__ float sigf(float x) { return 1.f / (1.f + __expf(-x)); }

// ---------------------------------------------------------------------------
// Row init: wn = ||w_row||, wc = wm = w
// ---------------------------------------------------------------------------
__global__ void k_row_init(const float* __restrict__ w, float* __restrict__ wc,
                           float* __restrict__ wm, float* __restrict__ wn, int len) {
    long row = blockIdx.x;
    const float* src = w + row * (long)len;
    float s = 0.f;
    for (int i = threadIdx.x; i < len; i += 256) {
        float x = src[i];
        s += x * x;
        wc[row * (long)len + i] = x;
        wm[row * (long)len + i] = x;
    }
    __shared__ float red[8];
    for (int o = 16; o; o >>= 1) s += __shfl_xor_sync(0xffffffffu, s, o);
    if ((threadIdx.x & 31) == 0) red[threadIdx.x >> 5] = s;
    __syncthreads();
    if (threadIdx.x == 0) {
        float tot = 0.f;
        for (int i = 0; i < 8; i++) tot += red[i];
        wn[row] = sqrtf(tot);
    }
}

// ---------------------------------------------------------------------------
// Row renorm: wc = wm / (||wm|| + eps) * wn
// Fused pair: blockIdx.y = 0 -> w0, 1 -> w2 (same shape). Used with len=DIN.
// Single variant (gridDim.y==1) used for w1 with len=DH.
// ---------------------------------------------------------------------------
__global__ void k_renorm2(const float* __restrict__ wmA, const float* __restrict__ wnA,
                          float* __restrict__ wcA,
                          const float* __restrict__ wmB, const float* __restrict__ wnB,
                          float* __restrict__ wcB, int len) {
    const float* wm = (blockIdx.y == 0) ? wmA : wmB;
    const float* wn = (blockIdx.y == 0) ? wnA : wnB;
    float*       wc = (blockIdx.y == 0) ? wcA : wcB;
    long row = blockIdx.x;
    const float* src = wm + row * (long)len;
    float s = 0.f;
    float vals[2];
    int cnt = 0;
    for (int i = threadIdx.x; i < len; i += 256) {
        float x = src[i];
        vals[cnt++] = x;
        s += x * x;
    }
    __shared__ float red[8];
    __shared__ float scale;
    for (int o = 16; o; o >>= 1) s += __shfl_xor_sync(0xffffffffu, s, o);
    if ((threadIdx.x & 31) == 0) red[threadIdx.x >> 5] = s;
    __syncthreads();
    if (threadIdx.x == 0) {
        float tot = 0.f;
        for (int i = 0; i < 8; i++) tot += red[i];
        scale = wn[row] / (sqrtf(tot) + 1e-5f);
    }
    __syncthreads();
    cnt = 0;
    for (int i = threadIdx.x; i < len; i += 256)
        wc[row * (long)len + i] = vals[cnt++] * scale;
}

// ---------------------------------------------------------------------------
// Dual NT GEMM: G = X @ W0^T, H = X @ W2^T   (M=CHK, N=DH, K=DIN)
// MODE 0: write O0 = silu(G)*H (q path).  MODE 1: write O0=G, O1=H (k path).
// ---------------------------------------------------------------------------
template <int MODE>
__global__ __launch_bounds__(256) void k_xw_dual(
    const float* __restrict__ X, long strideXb,
    const float* __restrict__ W0, const float* __restrict__ W2,
    float* __restrict__ O0, float* __restrict__ O1) {
    const int b  = blockIdx.z;
    const int m0 = blockIdx.x * 64;
    const int n0 = blockIdx.y * 64;
    const float* Xb  = X  + (long)b * strideXb;
    const float* W0b = W0 + (long)b * DH * DIN;
    const float* W2b = W2 + (long)b * DH * DIN;

    __shared__ float Xs[16][64];
    __shared__ float As[16][64];
    __shared__ float Bs[16][64];

    const int t  = threadIdx.x;
    const int tx = t & 15, ty = t >> 4;
    const int lm = t >> 2;         // 0..63
    const int lk = (t & 3) * 4;    // 0,4,8,12

    float a0[4][4] = {}, a1[4][4] = {};

    for (int k0 = 0; k0 < DIN; k0 += 16) {
        float4 xv  = *(const float4*)&Xb [(long)(m0 + lm) * DIN + k0 + lk];
        float4 wv0 = *(const float4*)&W0b[(long)(n0 + lm) * DIN + k0 + lk];
        float4 wv2 = *(const float4*)&W2b[(long)(n0 + lm) * DIN + k0 + lk];
        __syncthreads();
        Xs[lk + 0][lm] = xv.x;  Xs[lk + 1][lm] = xv.y;  Xs[lk + 2][lm] = xv.z;  Xs[lk + 3][lm] = xv.w;
        As[lk + 0][lm] = wv0.x; As[lk + 1][lm] = wv0.y; As[lk + 2][lm] = wv0.z; As[lk + 3][lm] = wv0.w;
        Bs[lk + 0][lm] = wv2.x; Bs[lk + 1][lm] = wv2.y; Bs[lk + 2][lm] = wv2.z; Bs[lk + 3][lm] = wv2.w;
        __syncthreads();
#pragma unroll
        for (int kk = 0; kk < 16; ++kk) {
            float4 xr  = *(const float4*)&Xs[kk][ty * 4];
            float4 w0r = *(const float4*)&As[kk][tx * 4];
            float4 w2r = *(const float4*)&Bs[kk][tx * 4];
            float xa[4] = {xr.x, xr.y, xr.z, xr.w};
            float wa[4] = {w0r.x, w0r.y, w0r.z, w0r.w};
            float wb[4] = {w2r.x, w2r.y, w2r.z, w2r.w};
#pragma unroll
            for (int i = 0; i < 4; i++)
#pragma unroll
                for (int j = 0; j < 4; j++) {
                    a0[i][j] += xa[i] * wa[j];
                    a1[i][j] += xa[i] * wb[j];
                }
        }
    }
#pragma unroll
    for (int i = 0; i < 4; i++) {
        int m = m0 + ty * 4 + i;
#pragma unroll
        for (int j = 0; j < 4; j++) {
            int nn = n0 + tx * 4 + j;
            long oidx = ((long)b * CHK + m) * DH + nn;
            float g = a0[i][j], h = a1[i][j];
            if (MODE == 0) {
                O0[oidx] = g * sigf(g) * h;
            } else {
                O0[oidx] = g;
                O1[oidx] = h;
            }
        }
    }
}

// ---------------------------------------------------------------------------
// NT GEMM: Out = U @ W1^T   (M=CHK, N=DOUT, K=DH). Out is strided (harness d_out).
// ---------------------------------------------------------------------------
__global__ __launch_bounds__(256) void k_uw1(
    const float* __restrict__ U, const float* __restrict__ W1,
    float* __restrict__ Out, long strideOb) {
    const int b  = blockIdx.z;
    const int m0 = blockIdx.x * 64;
    const int n0 = blockIdx.y * 64;
    const float* Ub  = U  + (long)b * CHK * DH;
    const float* W1b = W1 + (long)b * DOUT * DH;
    float* Ob = Out + (long)b * strideOb;

    __shared__ float Xs[16][64];
    __shared__ float Ws[16][64];

    const int t  = threadIdx.x;
    const int tx = t & 15, ty = t >> 4;
    const int lm = t >> 2;
    const int lk = (t & 3) * 4;

    float acc[4][4] = {};

    for (int k0 = 0; k0 < DH; k0 += 16) {
        float4 xv = *(const float4*)&Ub [(long)(m0 + lm) * DH + k0 + lk];
        float4 wv = *(const float4*)&W1b[(long)(n0 + lm) * DH + k0 + lk];
        __syncthreads();
        Xs[lk + 0][lm] = xv.x; Xs[lk + 1][lm] = xv.y; Xs[lk + 2][lm] = xv.z; Xs[lk + 3][lm] = xv.w;
        Ws[lk + 0][lm] = wv.x; Ws[lk + 1][lm] = wv.y; Ws[lk + 2][lm] = wv.z; Ws[lk + 3][lm] = wv.w;
        __syncthreads();
#pragma unroll
        for (int kk = 0; kk < 16; ++kk) {
            float4 xr = *(const float4*)&Xs[kk][ty * 4];
            float4 wr = *(const float4*)&Ws[kk][tx * 4];
            float xa[4] = {xr.x, xr.y, xr.z, xr.w};
            float wa[4] = {wr.x, wr.y, wr.z, wr.w};
#pragma unroll
            for (int i = 0; i < 4; i++)
#pragma unroll
                for (int j = 0; j < 4; j++) acc[i][j] += xa[i] * wa[j];
        }
    }
#pragma unroll
    for (int i = 0; i < 4; i++) {
        int m = m0 + ty * 4 + i;
#pragma unroll
        for (int j = 0; j < 4; j++)
            Ob[(long)m * DOUT + n0 + tx * 4 + j] = acc[i][j];
    }
}

// ---------------------------------------------------------------------------
// NN GEMM: D = V @ W1    (M=CHK, N=DH, K=DOUT).  dh[c,h] = sum_o v[c,o] w1[o,h]
// ---------------------------------------------------------------------------
__global__ __launch_bounds__(256) void k_vw1(
    const float* __restrict__ V, long strideVb,
    const float* __restrict__ W1, float* __restrict__ Dout_) {
    const int b  = blockIdx.z;
    const int m0 = blockIdx.x * 64;
    const int n0 = blockIdx.y * 64;
    const float* Vb  = V  + (long)b * strideVb;
    const float* W1b = W1 + (long)b * DOUT * DH;

    __shared__ float Xs[16][64];
    __shared__ float Ws[16][64];

    const int t  = threadIdx.x;
    const int tx = t & 15, ty = t >> 4;
    const int lm = t >> 2;
    const int lk = (t & 3) * 4;
    const int wk = t >> 4;          // 0..15
    const int wn = (t & 15) * 4;    // 0..60

    float acc[4][4] = {};

    for (int k0 = 0; k0 < DOUT; k0 += 16) {
        float4 xv = *(const float4*)&Vb [(long)(m0 + lm) * DOUT + k0 + lk];
        float4 wv = *(const float4*)&W1b[(long)(k0 + wk) * DH + n0 + wn];
        __syncthreads();
        Xs[lk + 0][lm] = xv.x; Xs[lk + 1][lm] = xv.y; Xs[lk + 2][lm] = xv.z; Xs[lk + 3][lm] = xv.w;
        *(float4*)&Ws[wk][wn] = wv;
        __syncthreads();
#pragma unroll
        for (int kk = 0; kk < 16; ++kk) {
            float4 xr = *(const float4*)&Xs[kk][ty * 4];
            float4 wr = *(const float4*)&Ws[kk][tx * 4];
            float xa[4] = {xr.x, xr.y, xr.z, xr.w};
            float wa[4] = {wr.x, wr.y, wr.z, wr.w};
#pragma unroll
            for (int i = 0; i < 4; i++)
#pragma unroll
                for (int j = 0; j < 4; j++) acc[i][j] += xa[i] * wa[j];
        }
    }
#pragma unroll
    for (int i = 0; i < 4; i++) {
        int m = m0 + ty * 4 + i;
#pragma unroll
        for (int j = 0; j < 4; j++)
            Dout_[((long)b * CHK + m) * DH + n0 + tx * 4 + j] = acc[i][j];
    }
}

// ---------------------------------------------------------------------------
// TN accumulate GEMM: C[m,n] += sum_c A[c,m] * B[c,n]   (K = CHK = 1024)
// ---------------------------------------------------------------------------
__global__ __launch_bounds__(256) void k_tn_acc(
    const float* __restrict__ A, long strideAb, int lda,
    const float* __restrict__ Bm, long strideBb, int ldb,
    float* __restrict__ Cacc, int M, int N) {
    const int b  = blockIdx.z;
    const int m0 = blockIdx.x * 64;
    const int n0 = blockIdx.y * 64;
    const float* Ab = A  + (long)b * strideAb;
    const float* Bb = Bm + (long)b * strideBb;
    float* Cb = Cacc + (long)b * M * N;

    __shared__ float As[16][64];
    __shared__ float Bs[16][64];

    const int t  = threadIdx.x;
    const int tx = t & 15, ty = t >> 4;
    const int lc = t >> 4;          // 0..15 (K rows)
    const int lq = (t & 15) * 4;    // 0..60

    float acc[4][4] = {};

    for (int c0 = 0; c0 < CHK; c0 += 16) {
        float4 av = *(const float4*)&Ab[(long)(c0 + lc) * lda + m0 + lq];
        float4 bv = *(const float4*)&Bb[(long)(c0 + lc) * ldb + n0 + lq];
        __syncthreads();
        *(float4*)&As[lc][lq] = av;
        *(float4*)&Bs[lc][lq] = bv;
        __syncthreads();
#pragma unroll
        for (int kk = 0; kk < 16; ++kk) {
            float4 ar = *(const float4*)&As[kk][ty * 4];
            float4 br = *(const float4*)&Bs[kk][tx * 4];
            float aa[4] = {ar.x, ar.y, ar.z, ar.w};
            float bb[4] = {br.x, br.y, br.z, br.w};
#pragma unroll
            for (int i = 0; i < 4; i++)
#pragma unroll
                for (int j = 0; j < 4; j++) acc[i][j] += aa[i] * bb[j];
        }
    }
#pragma unroll
    for (int i = 0; i < 4; i++) {
        long mrow = (long)(m0 + ty * 4 + i) * N;
#pragma unroll
        for (int j = 0; j < 4; j++)
            Cb[mrow + n0 + tx * 4 + j] += acc[i][j];
    }
}

// ---------------------------------------------------------------------------
// Fused SwiGLU backprop (in-place), folds per-token learning rates:
//   G  <- dgba * lr0,  HB <- dhbm * lr2,  D <- hidden * lr1
// ---------------------------------------------------------------------------
__global__ void k_bprop(const float* __restrict__ lr0, const float* __restrict__ lr1,
                        const float* __restrict__ lr2, int row0) {
    long idx = (long)blockIdx.x * 256 + threadIdx.x;  // BB*CHK*DH = 4194304
    int b = (int)(idx >> 19);             // CHK*DH = 2^19
    int c = (int)((idx >> 9) & (CHK - 1)); // DH = 2^9
    float g  = g_G[idx];
    float hb = g_HB[idx];
    float dh = g_D[idx];
    float s  = sigf(g);
    float sg = s * g;
    int li = b * LL + row0 + c;
    g_D [idx] = sg * hb * lr1[li];                          // hidden * lr1
    g_HB[idx] = dh * sg * lr2[li];                          // dhbm   * lr2
    float dg  = dh * hb;
    g_G [idx] = dg * s * (1.f + g * (1.f - s)) * lr0[li];   // dgba   * lr0
}

// ---------------------------------------------------------------------------
// Host launcher
// ---------------------------------------------------------------------------
extern "C" void kernel_launch(void* const* d_in, const int* in_sizes, int n_in,
                              void* d_out, int out_size) {
    const float* w0  = (const float*)d_in[0];
    const float* w1  = (const float*)d_in[1];
    const float* w2  = (const float*)d_in[2];
    const float* q   = (const float*)d_in[3];
    const float* kk  = (const float*)d_in[4];
    const float* v   = (const float*)d_in[5];
    const float* lr0 = (const float*)d_in[6];
    const float* lr1 = (const float*)d_in[7];
    const float* lr2 = (const float*)d_in[8];
    float* out = (float*)d_out;

    float *w0c, *w0m, *w1c, *w1m, *w2c, *w2m, *w0n, *w1n, *w2n, *G, *HB, *D, *U;
    cudaGetSymbolAddress((void**)&w0c, g_w0c);
    cudaGetSymbolAddress((void**)&w0m, g_w0m);
    cudaGetSymbolAddress((void**)&w1c, g_w1c);
    cudaGetSymbolAddress((void**)&w1m, g_w1m);
    cudaGetSymbolAddress((void**)&w2c, g_w2c);
    cudaGetSymbolAddress((void**)&w2m, g_w2m);
    cudaGetSymbolAddress((void**)&w0n, g_w0n);
    cudaGetSymbolAddress((void**)&w1n, g_w1n);
    cudaGetSymbolAddress((void**)&w2n, g_w2n);
    cudaGetSymbolAddress((void**)&G,   g_G);
    cudaGetSymbolAddress((void**)&HB,  g_HB);
    cudaGetSymbolAddress((void**)&D,   g_D);
    cudaGetSymbolAddress((void**)&U,   g_U);

    k_row_init<<<BB * DH, 256>>>(w0, w0c, w0m, w0n, DIN);
    k_row_init<<<BB * DOUT, 256>>>(w1, w1c, w1m, w1n, DH);
    k_row_init<<<BB * DH, 256>>>(w2, w2c, w2m, w2n, DIN);

    dim3 gApply(CHK / 64, DH / 64, BB);    // 16,8,8
    dim3 gOut(CHK / 64, DOUT / 64, BB);    // 16,4,8
    dim3 gNN(CHK / 64, DH / 64, BB);       // 16,8,8
    dim3 gDw(DH / 64, DIN / 64, BB);       // 8,4,8
    dim3 gDw1(DOUT / 64, DH / 64, BB);     // 4,8,8
    dim3 gRenorm02(BB * DH, 2, 1);         // fused w0+w2 renorm

    for (int i = 0; i < NCHK; ++i) {
        long off = (long)i * CHK;
        // apply current fast weights to queries (before update)
        k_xw_dual<0><<<gApply, 256>>>(q + off * DIN, (long)LL * DIN, w0c, w2c, U, nullptr);
        k_uw1<<<gOut, 256>>>(U, w1c, out + off * DOUT, (long)LL * DOUT);
        if (i == NCHK - 1) break;
        // key-path forward
        k_xw_dual<1><<<gApply, 256>>>(kk + off * DIN, (long)LL * DIN, w0c, w2c, G, HB);
        // dhidden = v @ w1
        k_vw1<<<gNN, 256>>>(v + off * DOUT, (long)LL * DOUT, w1c, D);
        // fused elementwise backprop + lr folding (in place)
        k_bprop<<<(BB * CHK * DH) / 256, 256>>>(lr0, lr1, lr2, (int)off);
        // weight gradient accumulation into main weights
        k_tn_acc<<<gDw1, 256>>>(v + off * DOUT, (long)LL * DOUT, DOUT,
                                D, (long)CHK * DH, DH, w1m, DOUT, DH);
        k_tn_acc<<<gDw, 256>>>(G, (long)CHK * DH, DH,
                               kk + off * DIN, (long)LL * DIN, DIN, w0m, DH, DIN);
        k_tn_acc<<<gDw, 256>>>(HB, (long)CHK * DH, DH,
                               kk + off * DIN, (long)LL * DIN, DIN, w2m, DH, DIN);
        // prenorm: renormalize rows of main weights into current weights
        k_renorm2<<<gRenorm02, 256>>>(w0m, w0n, w0c, w2m, w2n, w2c, DIN);
        k_renorm2<<<dim3(BB * DOUT, 1, 1), 256>>>(w1m, w1n, w1c, nullptr, nullptr, nullptr, DH);
    }
}

// round 9
// speedup vs baseline: 1.2631x; 1.2631x over previous
#include <cuda_runtime.h>
#include <cuda_bf16.h>
#include <cstdint>

// Problem shapes (fixed by dataset reference setup_inputs)
#define BB   8
#define LL   8192
#define DIN  256
#define DH   512
#define DOUT 256
#define CHK  1024
#define NCHK (LL / CHK)
#define SK   4            // split-K factor for dw GEMMs

// ---------------------------------------------------------------------------
// Scratch (device globals; no allocation allowed)
// ---------------------------------------------------------------------------
__device__ float g_w0c[BB * DH * DIN];
__device__ float g_w0m[BB * DH * DIN];
__device__ float g_w2c[BB * DH * DIN];
__device__ float g_w2m[BB * DH * DIN];
__device__ float g_w1c[BB * DOUT * DH];
__device__ float g_w1m[BB * DOUT * DH];
__device__ float g_w0n[BB * DH];
__device__ float g_w1n[BB * DOUT];
__device__ float g_w2n[BB * DH];
__device__ float g_G [BB * CHK * DH];   // gate_before_act   -> dgba*lr0
__device__ float g_HB[BB * CHK * DH];   // hidden_before_mul -> dhbm*lr2
__device__ float g_D [BB * CHK * DH];   // hidden*lr1 (for dw1)
__device__ float g_U [BB * CHK * DH];   // silu(g)*h for the q path
// split-K partial buffers
__device__ float g_P0[SK * BB * DH * DIN];
__device__ float g_P2[SK * BB * DH * DIN];
__device__ float g_P1[SK * BB * DOUT * DH];

__device__ __forceinline__ float sigf(float x) { return 1.f / (1.f + __expf(-x)); }

// Smem row paddings: MUST keep row stride a multiple of 4 floats (16 B) so that
// float4 LDS/STS at any k-row stay 16-byte aligned (misalignment = err715).
#define PA_ROW 132   // for 128-wide A tiles
#define PB_ROW 68    // for 64-wide tiles

// ---------------------------------------------------------------------------
// Row init: wn = ||w_row||, wc = wm = w
// ---------------------------------------------------------------------------
__global__ void k_row_init(const float* __restrict__ w, float* __restrict__ wc,
                           float* __restrict__ wm, float* __restrict__ wn, int len) {
    long row = blockIdx.x;
    const float* src = w + row * (long)len;
    float s = 0.f;
    for (int i = threadIdx.x; i < len; i += 256) {
        float x = src[i];
        s += x * x;
        wc[row * (long)len + i] = x;
        wm[row * (long)len + i] = x;
    }
    __shared__ float red[8];
    for (int o = 16; o; o >>= 1) s += __shfl_xor_sync(0xffffffffu, s, o);
    if ((threadIdx.x & 31) == 0) red[threadIdx.x >> 5] = s;
    __syncthreads();
    if (threadIdx.x == 0) {
        float tot = 0.f;
        for (int i = 0; i < 8; i++) tot += red[i];
        wn[row] = sqrtf(tot);
    }
}

// ---------------------------------------------------------------------------
// Fused split-K reduce + prenorm renorm.
//   wm[row] += sum_s P[s][row];  wc[row] = wm[row]/(||wm row||+eps)*wn[row]
// blockIdx.y selects weight-set A or B (pair launch for w0/w2).
// ---------------------------------------------------------------------------
__global__ void k_rr(const float* __restrict__ PA, float* __restrict__ wmA,
                     const float* __restrict__ wnA, float* __restrict__ wcA,
                     const float* __restrict__ PB, float* __restrict__ wmB,
                     const float* __restrict__ wnB, float* __restrict__ wcB,
                     int L, long tot) {
    const float* P  = blockIdx.y ? PB : PA;
    float*       wm = blockIdx.y ? wmB : wmA;
    const float* wn = blockIdx.y ? wnB : wnA;
    float*       wc = blockIdx.y ? wcB : wcA;
    long row = blockIdx.x;
    float vals[2];
    int cnt = 0;
    float s = 0.f;
    for (int i = threadIdx.x; i < L; i += 256) {
        long idx = row * (long)L + i;
        float v = wm[idx];
#pragma unroll
        for (int k = 0; k < SK; k++) v += P[(long)k * tot + idx];
        wm[idx] = v;
        vals[cnt++] = v;
        s += v * v;
    }
    __shared__ float red[8];
    __shared__ float scale;
    for (int o = 16; o; o >>= 1) s += __shfl_xor_sync(0xffffffffu, s, o);
    if ((threadIdx.x & 31) == 0) red[threadIdx.x >> 5] = s;
    __syncthreads();
    if (threadIdx.x == 0) {
        float tot2 = 0.f;
        for (int i = 0; i < 8; i++) tot2 += red[i];
        scale = wn[row] / (sqrtf(tot2) + 1e-5f);
    }
    __syncthreads();
    cnt = 0;
    for (int i = threadIdx.x; i < L; i += 256)
        wc[row * (long)L + i] = vals[cnt++] * scale;
}

// ---------------------------------------------------------------------------
// Dual NT GEMM, 64x64 tile, double buffered: G = X@W0^T, H = X@W2^T
// M=CHK, N=DH, K=DIN. MODE 0: O0 = silu(G)*H.  MODE 1: O0=G, O1=H.
// ---------------------------------------------------------------------------
template <int MODE>
__global__ __launch_bounds__(256, 3) void k_dual(
    const float* __restrict__ X,   // pre-offset to chunk start; batch stride LL*DIN
    const float* __restrict__ W0, const float* __restrict__ W2,
    float* __restrict__ O0, float* __restrict__ O1) {
    const int b  = blockIdx.z;
    const int m0 = blockIdx.x * 64;
    const int n0 = blockIdx.y * 64;
    const float* Xb  = X  + (long)b * LL * DIN;
    const float* W0b = W0 + (long)b * DH * DIN;
    const float* W2b = W2 + (long)b * DH * DIN;

    __shared__ float As [2][16][PB_ROW];
    __shared__ float B0s[2][16][PB_ROW];
    __shared__ float B1s[2][16][PB_ROW];

    const int t  = threadIdx.x;
    const int tx = t & 15, ty = t >> 4;
    const int lr = t >> 2;         // 0..63
    const int lc = (t & 3) * 4;    // 0,4,8,12

    float a0[4][4] = {}, a1[4][4] = {};
    float4 ra, rb0, rb1;

    // prologue: load k-block 0
    ra  = *(const float4*)&Xb [(long)(m0 + lr) * DIN + lc];
    rb0 = *(const float4*)&W0b[(long)(n0 + lr) * DIN + lc];
    rb1 = *(const float4*)&W2b[(long)(n0 + lr) * DIN + lc];
    As [0][lc + 0][lr] = ra.x;  As [0][lc + 1][lr] = ra.y;  As [0][lc + 2][lr] = ra.z;  As [0][lc + 3][lr] = ra.w;
    B0s[0][lc + 0][lr] = rb0.x; B0s[0][lc + 1][lr] = rb0.y; B0s[0][lc + 2][lr] = rb0.z; B0s[0][lc + 3][lr] = rb0.w;
    B1s[0][lc + 0][lr] = rb1.x; B1s[0][lc + 1][lr] = rb1.y; B1s[0][lc + 2][lr] = rb1.z; B1s[0][lc + 3][lr] = rb1.w;
    __syncthreads();

    const int NKB = DIN / 16;
    for (int kb = 0; kb < NKB; ++kb) {
        const int buf = kb & 1;
        if (kb + 1 < NKB) {
            const int k0 = (kb + 1) * 16;
            ra  = *(const float4*)&Xb [(long)(m0 + lr) * DIN + k0 + lc];
            rb0 = *(const float4*)&W0b[(long)(n0 + lr) * DIN + k0 + lc];
            rb1 = *(const float4*)&W2b[(long)(n0 + lr) * DIN + k0 + lc];
        }
#pragma unroll
        for (int kk = 0; kk < 16; ++kk) {
            float4 av = *(const float4*)&As [buf][kk][ty * 4];
            float4 b0 = *(const float4*)&B0s[buf][kk][tx * 4];
            float4 b1 = *(const float4*)&B1s[buf][kk][tx * 4];
            float xa[4] = {av.x, av.y, av.z, av.w};
            float wa[4] = {b0.x, b0.y, b0.z, b0.w};
            float wb[4] = {b1.x, b1.y, b1.z, b1.w};
#pragma unroll
            for (int i = 0; i < 4; i++)
#pragma unroll
                for (int j = 0; j < 4; j++) {
                    a0[i][j] += xa[i] * wa[j];
                    a1[i][j] += xa[i] * wb[j];
                }
        }
        if (kb + 1 < NKB) {
            const int nb = buf ^ 1;
            As [nb][lc + 0][lr] = ra.x;  As [nb][lc + 1][lr] = ra.y;  As [nb][lc + 2][lr] = ra.z;  As [nb][lc + 3][lr] = ra.w;
            B0s[nb][lc + 0][lr] = rb0.x; B0s[nb][lc + 1][lr] = rb0.y; B0s[nb][lc + 2][lr] = rb0.z; B0s[nb][lc + 3][lr] = rb0.w;
            B1s[nb][lc + 0][lr] = rb1.x; B1s[nb][lc + 1][lr] = rb1.y; B1s[nb][lc + 2][lr] = rb1.z; B1s[nb][lc + 3][lr] = rb1.w;
            __syncthreads();
        }
    }

#pragma unroll
    for (int i = 0; i < 4; i++) {
        const int m = m0 + ty * 4 + i;
        long rowb = ((long)b * CHK + m) * DH + n0 + tx * 4;
        if (MODE == 0) {
            float4 o;
            o.x = a0[i][0] * sigf(a0[i][0]) * a1[i][0];
            o.y = a0[i][1] * sigf(a0[i][1]) * a1[i][1];
            o.z = a0[i][2] * sigf(a0[i][2]) * a1[i][2];
            o.w = a0[i][3] * sigf(a0[i][3]) * a1[i][3];
            *(float4*)&O0[rowb] = o;
        } else {
            *(float4*)&O0[rowb] = make_float4(a0[i][0], a0[i][1], a0[i][2], a0[i][3]);
            *(float4*)&O1[rowb] = make_float4(a1[i][0], a1[i][1], a1[i][2], a1[i][3]);
        }
    }
}

// ---------------------------------------------------------------------------
// 128x64 double-buffered GEMM mainloop (device core).
// AL=0: A is [M,Ktot] row-major. AL=1: A is [Ktot,M].
// BL=0: B is [N,Ktot] row-major (NT). BL=1: B is [Ktot,N] (NN).
// Computes acc[8][4] for output tile (m0+ty*8+i, n0+tx*4+j).
// ---------------------------------------------------------------------------
template <int AL, int BL>
__device__ __forceinline__ void gemm_core(
    const float* __restrict__ Ab, int lda,
    const float* __restrict__ Bb, int ldb,
    int m0, int n0, int kStart, int nkb,
    float acc[8][4],
    float (&As)[2][16][PA_ROW], float (&Bs)[2][16][PB_ROW]) {
    const int t  = threadIdx.x;
    const int tx = t & 15, ty = t >> 4;
    const int lr = t >> 2;          // 0..63
    const int lc = (t & 3) * 4;     // 0,4,8,12
    const int kq = t >> 4;          // 0..15
    const int q4 = (t & 15) * 4;    // 0..60

    float4 ra0, ra1, rb;

#define LD_TILE(K0)                                                              \
    {                                                                            \
        if (AL == 0) {                                                           \
            ra0 = *(const float4*)&Ab[(long)(m0 + lr) * lda + (K0) + lc];        \
            ra1 = *(const float4*)&Ab[(long)(m0 + lr + 64) * lda + (K0) + lc];   \
        } else {                                                                 \
            ra0 = *(const float4*)&Ab[(long)((K0) + kq) * lda + m0 + q4];        \
            ra1 = *(const float4*)&Ab[(long)((K0) + kq) * lda + m0 + q4 + 64];   \
        }                                                                        \
        if (BL == 0) {                                                           \
            rb = *(const float4*)&Bb[(long)(n0 + lr) * ldb + (K0) + lc];         \
        } else {                                                                 \
            rb = *(const float4*)&Bb[(long)((K0) + kq) * ldb + n0 + q4];         \
        }                                                                        \
    }

#define ST_TILE(BF)                                                              \
    {                                                                            \
        if (AL == 0) {                                                           \
            As[BF][lc + 0][lr] = ra0.x; As[BF][lc + 1][lr] = ra0.y;              \
            As[BF][lc + 2][lr] = ra0.z; As[BF][lc + 3][lr] = ra0.w;              \
            As[BF][lc + 0][lr + 64] = ra1.x; As[BF][lc + 1][lr + 64] = ra1.y;    \
            As[BF][lc + 2][lr + 64] = ra1.z; As[BF][lc + 3][lr + 64] = ra1.w;    \
        } else {                                                                 \
            *(float4*)&As[BF][kq][q4] = ra0;                                     \
            *(float4*)&As[BF][kq][q4 + 64] = ra1;                                \
        }                                                                        \
        if (BL == 0) {                                                           \
            Bs[BF][lc + 0][lr] = rb.x; Bs[BF][lc + 1][lr] = rb.y;                \
            Bs[BF][lc + 2][lr] = rb.z; Bs[BF][lc + 3][lr] = rb.w;                \
        } else {                                                                 \
            *(float4*)&Bs[BF][kq][q4] = rb;                                      \
        }                                                                        \
    }

    LD_TILE(kStart);
    ST_TILE(0);
    __syncthreads();

    for (int kb = 0; kb < nkb; ++kb) {
        const int buf = kb & 1;
        if (kb + 1 < nkb) LD_TILE(kStart + (kb + 1) * 16);
#pragma unroll
        for (int kk = 0; kk < 16; ++kk) {
            float4 x0 = *(const float4*)&As[buf][kk][ty * 8];
            float4 x1 = *(const float4*)&As[buf][kk][ty * 8 + 4];
            float4 bv = *(const float4*)&Bs[buf][kk][tx * 4];
            float xa[8] = {x0.x, x0.y, x0.z, x0.w, x1.x, x1.y, x1.z, x1.w};
            float wb[4] = {bv.x, bv.y, bv.z, bv.w};
#pragma unroll
            for (int i = 0; i < 8; i++)
#pragma unroll
                for (int j = 0; j < 4; j++) acc[i][j] += xa[i] * wb[j];
        }
        if (kb + 1 < nkb) {
            ST_TILE(buf ^ 1);
            __syncthreads();
        }
    }
#undef LD_TILE
#undef ST_TILE
}

// ---------------------------------------------------------------------------
// Out = U @ W1^T  (M=CHK, N=DOUT, K=DH). Out pre-offset to chunk.
// ---------------------------------------------------------------------------
__global__ __launch_bounds__(256, 3) void k_uw1(
    const float* __restrict__ U, const float* __restrict__ W1, float* __restrict__ O) {
    const int b  = blockIdx.z;
    const int m0 = blockIdx.x * 128;
    const int n0 = blockIdx.y * 64;
    __shared__ float As[2][16][PA_ROW];
    __shared__ float Bs[2][16][PB_ROW];
    float acc[8][4] = {};
    gemm_core<0, 0>(U + (long)b * CHK * DH, DH,
                    W1 + (long)b * DOUT * DH, DH,
                    m0, n0, 0, DH / 16, acc, As, Bs);
    const int tx = threadIdx.x & 15, ty = threadIdx.x >> 4;
    float* Ob = O + (long)b * LL * DOUT;
#pragma unroll
    for (int i = 0; i < 8; i++) {
        const int m = m0 + ty * 8 + i;
        *(float4*)&Ob[(long)m * DOUT + n0 + tx * 4] =
            make_float4(acc[i][0], acc[i][1], acc[i][2], acc[i][3]);
    }
}

// ---------------------------------------------------------------------------
// D = V @ W1 (M=CHK, N=DH, K=DOUT), fused SwiGLU backprop epilogue:
//   reads G (gate), HB (hidden_before_mul); writes
//   G <- dgba*lr0, HB <- dhbm*lr2, D <- hidden*lr1
// ---------------------------------------------------------------------------
__global__ __launch_bounds__(256, 3) void k_vw1bp(
    const float* __restrict__ V,   // pre-offset to chunk; batch stride LL*DOUT
    const float* __restrict__ W1,
    float* __restrict__ G, float* __restrict__ HB, float* __restrict__ D,
    const float* __restrict__ lr0, const float* __restrict__ lr1,
    const float* __restrict__ lr2, int row0) {
    const int b  = blockIdx.z;
    const int m0 = blockIdx.x * 128;
    const int n0 = blockIdx.y * 64;
    __shared__ float As[2][16][PA_ROW];
    __shared__ float Bs[2][16][PB_ROW];
    float acc[8][4] = {};
    gemm_core<0, 1>(V + (long)b * LL * DOUT, DOUT,
                    W1 + (long)b * DOUT * DH, DH,
                    m0, n0, 0, DOUT / 16, acc, As, Bs);
    const int tx = threadIdx.x & 15, ty = threadIdx.x >> 4;
#pragma unroll
    for (int i = 0; i < 8; i++) {
        const int m = m0 + ty * 8 + i;
        const int li = b * LL + row0 + m;
        const float l0 = lr0[li], l1 = lr1[li], l2 = lr2[li];
        long idx = ((long)b * CHK + m) * DH + n0 + tx * 4;
        float4 gv  = *(const float4*)&G [idx];
        float4 hbv = *(const float4*)&HB[idx];
        float go[4], ho[4], dv[4];
        float ga[4] = {gv.x, gv.y, gv.z, gv.w};
        float ha[4] = {hbv.x, hbv.y, hbv.z, hbv.w};
#pragma unroll
        for (int j = 0; j < 4; j++) {
            float g  = ga[j];
            float hb = ha[j];
            float dh = acc[i][j];
            float s  = sigf(g);
            float sg = s * g;
            dv[j] = sg * hb * l1;                            // hidden * lr1
            ho[j] = dh * sg * l2;                            // dhbm   * lr2
            go[j] = dh * hb * s * (1.f + g * (1.f - s)) * l0; // dgba  * lr0
        }
        *(float4*)&D [idx] = make_float4(dv[0], dv[1], dv[2], dv[3]);
        *(float4*)&HB[idx] = make_float4(ho[0], ho[1], ho[2], ho[3]);
        *(float4*)&G [idx] = make_float4(go[0], go[1], go[2], go[3]);
    }
}

// ---------------------------------------------------------------------------
// Split-K TN GEMM: P[s][b][m][n] = sum_{c in split s} A[c,m] * B[c,n]
// A: [CHK, M] (lda), batch stride sAb. B: [CHK, N] (ldb), batch stride sBb.
// blockIdx.z = b*SK + s.
// ---------------------------------------------------------------------------
__global__ __launch_bounds__(256, 3) void k_tn(
    const float* __restrict__ A, long sAb, int lda,
    const float* __restrict__ B, long sBb, int ldb,
    float* __restrict__ P, int M, int N) {
    const int zz = blockIdx.z;
    const int b  = zz >> 2;      // SK = 4
    const int s  = zz & 3;
    const int m0 = blockIdx.x * 128;
    const int n0 = blockIdx.y * 64;
    __shared__ float As[2][16][PA_ROW];
    __shared__ float Bs[2][16][PB_ROW];
    float acc[8][4] = {};
    gemm_core<1, 1>(A + (long)b * sAb, lda,
                    B + (long)b * sBb, ldb,
                    m0, n0, s * (CHK / SK), (CHK / SK) / 16, acc, As, Bs);
    const int tx = threadIdx.x & 15, ty = threadIdx.x >> 4;
    float* Pb = P + ((long)s * BB + b) * ((long)M * N);
#pragma unroll
    for (int i = 0; i < 8; i++) {
        const int m = m0 + ty * 8 + i;
        *(float4*)&Pb[(long)m * N + n0 + tx * 4] =
            make_float4(acc[i][0], acc[i][1], acc[i][2], acc[i][3]);
    }
}

// ---------------------------------------------------------------------------
// Host launcher
// ---------------------------------------------------------------------------
extern "C" void kernel_launch(void* const* d_in, const int* in_sizes, int n_in,
                              void* d_out, int out_size) {
    const float* w0  = (const float*)d_in[0];
    const float* w1  = (const float*)d_in[1];
    const float* w2  = (const float*)d_in[2];
    const float* q   = (const float*)d_in[3];
    const float* kk  = (const float*)d_in[4];
    const float* v   = (const float*)d_in[5];
    const float* lr0 = (const float*)d_in[6];
    const float* lr1 = (const float*)d_in[7];
    const float* lr2 = (const float*)d_in[8];
    float* out = (float*)d_out;

    float *w0c, *w0m, *w1c, *w1m, *w2c, *w2m, *w0n, *w1n, *w2n;
    float *G, *HB, *D, *U, *P0, *P2, *P1;
    cudaGetSymbolAddress((void**)&w0c, g_w0c);
    cudaGetSymbolAddress((void**)&w0m, g_w0m);
    cudaGetSymbolAddress((void**)&w1c, g_w1c);
    cudaGetSymbolAddress((void**)&w1m, g_w1m);
    cudaGetSymbolAddress((void**)&w2c, g_w2c);
    cudaGetSymbolAddress((void**)&w2m, g_w2m);
    cudaGetSymbolAddress((void**)&w0n, g_w0n);
    cudaGetSymbolAddress((void**)&w1n, g_w1n);
    cudaGetSymbolAddress((void**)&w2n, g_w2n);
    cudaGetSymbolAddress((void**)&G,   g_G);
    cudaGetSymbolAddress((void**)&HB,  g_HB);
    cudaGetSymbolAddress((void**)&D,   g_D);
    cudaGetSymbolAddress((void**)&U,   g_U);
    cudaGetSymbolAddress((void**)&P0,  g_P0);
    cudaGetSymbolAddress((void**)&P2,  g_P2);
    cudaGetSymbolAddress((void**)&P1,  g_P1);

    k_row_init<<<BB * DH, 256>>>(w0, w0c, w0m, w0n, DIN);
    k_row_init<<<BB * DOUT, 256>>>(w1, w1c, w1m, w1n, DH);
    k_row_init<<<BB * DH, 256>>>(w2, w2c, w2m, w2n, DIN);

    dim3 gDual(CHK / 64, DH / 64, BB);        // 16,8,8
    dim3 gU(CHK / 128, DOUT / 64, BB);        // 8,4,8
    dim3 gV(CHK / 128, DH / 64, BB);          // 8,8,8
    dim3 gDw02(DH / 128, DIN / 64, BB * SK);  // 4,4,32
    dim3 gDw1(DOUT / 128, DH / 64, BB * SK);  // 2,8,32
    dim3 gRR02(BB * DH, 2, 1);
    dim3 gRR1(BB * DOUT, 1, 1);

    for (int i = 0; i < NCHK; ++i) {
        long off = (long)i * CHK;
        // apply current fast weights to queries (before update)
        k_dual<0><<<gDual, 256>>>(q + off * DIN, w0c, w2c, U, nullptr);
        k_uw1<<<gU, 256>>>(U, w1c, out + off * DOUT);
        if (i == NCHK - 1) break;
        // key-path forward: G = gate_before_act, HB = hidden_before_mul
        k_dual<1><<<gDual, 256>>>(kk + off * DIN, w0c, w2c, G, HB);
        // dhidden = v @ w1, fused SwiGLU backprop + lr folding
        k_vw1bp<<<gV, 256>>>(v + off * DOUT, w1c, G, HB, D, lr0, lr1, lr2, (int)off);
        // split-K weight gradients (pure partial writes; deterministic)
        k_tn<<<gDw02, 256>>>(G,  (long)CHK * DH, DH,
                             kk + off * DIN, (long)LL * DIN, DIN, P0, DH, DIN);
        k_tn<<<gDw02, 256>>>(HB, (long)CHK * DH, DH,
                             kk + off * DIN, (long)LL * DIN, DIN, P2, DH, DIN);
        k_tn<<<gDw1, 256>>>(v + off * DOUT, (long)LL * DOUT, DOUT,
                            D, (long)CHK * DH, DH, P1, DOUT, DH);
        // fused reduce + prenorm renorm
        k_rr<<<gRR02, 256>>>(P0, w0m, w0n, w0c, P2, w2m, w2n, w2c,
                             DIN, (long)BB * DH * DIN);
        k_rr<<<gRR1, 256>>>(P1, w1m, w1n, w1c, nullptr, nullptr, nullptr, nullptr,
                            DH, (long)BB * DOUT * DH);
    }
}

// round 11
// speedup vs baseline: 1.3200x; 1.0450x over previous
#include <cuda_runtime.h>
#include <cuda_bf16.h>
#include <cstdint>

// Problem shapes (fixed by dataset reference setup_inputs)
#define BB   8
#define LL   8192
#define DIN  256
#define DH   512
#define DOUT 256
#define CHK  1024
#define NCHK (LL / CHK)
#define SK   4            // split-K factor for dw GEMMs

// ---------------------------------------------------------------------------
// Scratch (device globals; no allocation allowed)
// ---------------------------------------------------------------------------
__device__ float g_w0c[BB * DH * DIN];
__device__ float g_w0m[BB * DH * DIN];
__device__ float g_w2c[BB * DH * DIN];
__device__ float g_w2m[BB * DH * DIN];
__device__ float g_w1c[BB * DOUT * DH];
__device__ float g_w1m[BB * DOUT * DH];
__device__ float g_w0n[BB * DH];
__device__ float g_w1n[BB * DOUT];
__device__ float g_w2n[BB * DH];
__device__ float g_G [BB * CHK * DH];   // gate_before_act   -> dgba*lr0
__device__ float g_HB[BB * CHK * DH];   // hidden_before_mul -> dhbm*lr2
__device__ float g_D [BB * CHK * DH];   // hidden*lr1 (for dw1)
__device__ float g_U [BB * CHK * DH];   // silu(g)*h for the q path
// split-K partial buffers
__device__ float g_P0[SK * BB * DH * DIN];
__device__ float g_P2[SK * BB * DH * DIN];
__device__ float g_P1[SK * BB * DOUT * DH];

__device__ __forceinline__ float sigf(float x) { return 1.f / (1.f + __expf(-x)); }

// Smem row paddings (row stride MUST stay multiple of 4 floats = 16 B so all
// float4 LDS/STS stay aligned; misalignment = err715).
#define PA_ROW 132   // 128-wide tiles (g128 core + old gemm_core A)
#define PB_ROW 68    // 64-wide tiles (old gemm_core B)

// ---------------------------------------------------------------------------
// Row init: wn = ||w_row||, wc = wm = w
// ---------------------------------------------------------------------------
__global__ void k_row_init(const float* __restrict__ w, float* __restrict__ wc,
                           float* __restrict__ wm, float* __restrict__ wn, int len) {
    long row = blockIdx.x;
    const float* src = w + row * (long)len;
    float s = 0.f;
    for (int i = threadIdx.x; i < len; i += 256) {
        float x = src[i];
        s += x * x;
        wc[row * (long)len + i] = x;
        wm[row * (long)len + i] = x;
    }
    __shared__ float red[8];
    for (int o = 16; o; o >>= 1) s += __shfl_xor_sync(0xffffffffu, s, o);
    if ((threadIdx.x & 31) == 0) red[threadIdx.x >> 5] = s;
    __syncthreads();
    if (threadIdx.x == 0) {
        float tot = 0.f;
        for (int i = 0; i < 8; i++) tot += red[i];
        wn[row] = sqrtf(tot);
    }
}

// ---------------------------------------------------------------------------
// Fused split-K reduce + prenorm renorm.
// ---------------------------------------------------------------------------
__global__ void k_rr(const float* __restrict__ PA, float* __restrict__ wmA,
                     const float* __restrict__ wnA, float* __restrict__ wcA,
                     const float* __restrict__ PB, float* __restrict__ wmB,
                     const float* __restrict__ wnB, float* __restrict__ wcB,
                     int L, long tot) {
    const float* P  = blockIdx.y ? PB : PA;
    float*       wm = blockIdx.y ? wmB : wmA;
    const float* wn = blockIdx.y ? wnB : wnA;
    float*       wc = blockIdx.y ? wcB : wcA;
    long row = blockIdx.x;
    float vals[2];
    int cnt = 0;
    float s = 0.f;
    for (int i = threadIdx.x; i < L; i += 256) {
        long idx = row * (long)L + i;
        float v = wm[idx];
#pragma unroll
        for (int k = 0; k < SK; k++) v += P[(long)k * tot + idx];
        wm[idx] = v;
        vals[cnt++] = v;
        s += v * v;
    }
    __shared__ float red[8];
    __shared__ float scale;
    for (int o = 16; o; o >>= 1) s += __shfl_xor_sync(0xffffffffu, s, o);
    if ((threadIdx.x & 31) == 0) red[threadIdx.x >> 5] = s;
    __syncthreads();
    if (threadIdx.x == 0) {
        float tot2 = 0.f;
        for (int i = 0; i < 8; i++) tot2 += red[i];
        scale = wn[row] / (sqrtf(tot2) + 1e-5f);
    }
    __syncthreads();
    cnt = 0;
    for (int i = threadIdx.x; i < L; i += 256)
        wc[row * (long)L + i] = vals[cnt++] * scale;
}

// ---------------------------------------------------------------------------
// g128 core: 128x128 tile, 256 threads, 8x8 per thread, double buffered.
// AL/BL: 0 = ROW layout ([rows, Ktot] row-major, rows = M or N; transposed
//        into smem), 1 = COL layout ([Ktot, width] k-major; direct copy).
// Smem holds [k][m] / [k][n]. Thread (tx=t&15, ty=t>>4) owns rows
// m0+ty*8+i (i<8) and cols n0+tx*4+j (j<4) plus n0+64+tx*4+j (j 4..7).
// ---------------------------------------------------------------------------
template <int AL, int BL>
__device__ __forceinline__ void g128_core(
    const float* __restrict__ Ab, int lda,
    const float* __restrict__ Bb, int ldb,
    int m0, int n0, int kStart, int nkb,
    float acc[8][8],
    float (&As)[2][16][PA_ROW], float (&Bs)[2][16][PA_ROW]) {
    const int t  = threadIdx.x;
    const int rr = t >> 1;          // ROW loader: tile row 0..127
    const int rc = (t & 1) * 8;     // ROW loader: k offset 0 or 8
    const int kr = t >> 4;          // COL loader: k row 0..15
    const int cc = (t & 15) * 8;    // COL loader: col offset 0..120
    const int tx = t & 15, ty = t >> 4;

    float4 a0v, a1v, b0v, b1v;

#define G_LD(K0)                                                                  \
    {                                                                             \
        if (AL == 0) {                                                            \
            a0v = *(const float4*)&Ab[(long)(m0 + rr) * lda + (K0) + rc];         \
            a1v = *(const float4*)&Ab[(long)(m0 + rr) * lda + (K0) + rc + 4];     \
        } else {                                                                  \
            a0v = *(const float4*)&Ab[(long)((K0) + kr) * lda + m0 + cc];         \
            a1v = *(const float4*)&Ab[(long)((K0) + kr) * lda + m0 + cc + 4];     \
        }                                                                         \
        if (BL == 0) {                                                            \
            b0v = *(const float4*)&Bb[(long)(n0 + rr) * ldb + (K0) + rc];         \
            b1v = *(const float4*)&Bb[(long)(n0 + rr) * ldb + (K0) + rc + 4];     \
        } else {                                                                  \
            b0v = *(const float4*)&Bb[(long)((K0) + kr) * ldb + n0 + cc];         \
            b1v = *(const float4*)&Bb[(long)((K0) + kr) * ldb + n0 + cc + 4];     \
        }                                                                         \
    }

#define G_ST(BF)                                                                  \
    {                                                                             \
        if (AL == 0) {                                                            \
            As[BF][rc + 0][rr] = a0v.x; As[BF][rc + 1][rr] = a0v.y;               \
            As[BF][rc + 2][rr] = a0v.z; As[BF][rc + 3][rr] = a0v.w;               \
            As[BF][rc + 4][rr] = a1v.x; As[BF][rc + 5][rr] = a1v.y;               \
            As[BF][rc + 6][rr] = a1v.z; As[BF][rc + 7][rr] = a1v.w;               \
        } else {                                                                  \
            *(float4*)&As[BF][kr][cc]     = a0v;                                  \
            *(float4*)&As[BF][kr][cc + 4] = a1v;                                  \
        }                                                                         \
        if (BL == 0) {                                                            \
            Bs[BF][rc + 0][rr] = b0v.x; Bs[BF][rc + 1][rr] = b0v.y;               \
            Bs[BF][rc + 2][rr] = b0v.z; Bs[BF][rc + 3][rr] = b0v.w;               \
            Bs[BF][rc + 4][rr] = b1v.x; Bs[BF][rc + 5][rr] = b1v.y;               \
            Bs[BF][rc + 6][rr] = b1v.z; Bs[BF][rc + 7][rr] = b1v.w;               \
        } else {                                                                  \
            *(float4*)&Bs[BF][kr][cc]     = b0v;                                  \
            *(float4*)&Bs[BF][kr][cc + 4] = b1v;                                  \
        }                                                                         \
    }

    G_LD(kStart);
    G_ST(0);
    __syncthreads();

    for (int kb = 0; kb < nkb; ++kb) {
        const int buf = kb & 1;
        if (kb + 1 < nkb) G_LD(kStart + (kb + 1) * 16);
#pragma unroll
        for (int kk = 0; kk < 16; ++kk) {
            float4 xa0 = *(const float4*)&As[buf][kk][ty * 8];
            float4 xa1 = *(const float4*)&As[buf][kk][ty * 8 + 4];
            float4 xb0 = *(const float4*)&Bs[buf][kk][tx * 4];
            float4 xb1 = *(const float4*)&Bs[buf][kk][64 + tx * 4];
            float av[8] = {xa0.x, xa0.y, xa0.z, xa0.w, xa1.x, xa1.y, xa1.z, xa1.w};
            float bv[8] = {xb0.x, xb0.y, xb0.z, xb0.w, xb1.x, xb1.y, xb1.z, xb1.w};
#pragma unroll
            for (int i = 0; i < 8; i++)
#pragma unroll
                for (int j = 0; j < 8; j++) acc[i][j] += av[i] * bv[j];
        }
        if (kb + 1 < nkb) {
            G_ST(buf ^ 1);
            __syncthreads();
        }
    }
#undef G_LD
#undef G_ST
}

// ---------------------------------------------------------------------------
// NT GEMM, plain store: C = A @ B^T  (A ROW [M,K], B ROW [N,K]).
// Used for: G = X @ W0^T  and  HB = X @ W2^T  (k path / q path G).
// ---------------------------------------------------------------------------
__global__ __launch_bounds__(256, 2) void k_nt(
    const float* __restrict__ A, long sAb, int lda,
    const float* __restrict__ B, long sBb, int ldb,
    float* __restrict__ C, long sCb, int ldc, int nkb) {
    const int b  = blockIdx.z;
    const int m0 = blockIdx.x * 128;
    const int n0 = blockIdx.y * 128;
    __shared__ float As[2][16][PA_ROW];
    __shared__ float Bs[2][16][PA_ROW];
    float acc[8][8] = {};
    g128_core<0, 0>(A + (long)b * sAb, lda, B + (long)b * sBb, ldb,
                    m0, n0, 0, nkb, acc, As, Bs);
    const int tx = threadIdx.x & 15, ty = threadIdx.x >> 4;
    float* Cb = C + (long)b * sCb;
#pragma unroll
    for (int i = 0; i < 8; i++) {
        long base = (long)(m0 + ty * 8 + i) * ldc;
        *(float4*)&Cb[base + n0 + tx * 4] =
            make_float4(acc[i][0], acc[i][1], acc[i][2], acc[i][3]);
        *(float4*)&Cb[base + n0 + 64 + tx * 4] =
            make_float4(acc[i][4], acc[i][5], acc[i][6], acc[i][7]);
    }
}

// ---------------------------------------------------------------------------
// NT GEMM with SiLU-mul epilogue: U = silu(Gprev) * (A @ B^T).
// Used for the q path H GEMM (Gprev = q-path gate, written by k_nt just before).
// ---------------------------------------------------------------------------
__global__ __launch_bounds__(256, 2) void k_nt_silu(
    const float* __restrict__ A, long sAb, int lda,
    const float* __restrict__ B, long sBb, int ldb,
    const float* __restrict__ Gp, float* __restrict__ U,
    long sCb, int ldc, int nkb) {
    const int b  = blockIdx.z;
    const int m0 = blockIdx.x * 128;
    const int n0 = blockIdx.y * 128;
    __shared__ float As[2][16][PA_ROW];
    __shared__ float Bs[2][16][PA_ROW];
    float acc[8][8] = {};
    g128_core<0, 0>(A + (long)b * sAb, lda, B + (long)b * sBb, ldb,
                    m0, n0, 0, nkb, acc, As, Bs);
    const int tx = threadIdx.x & 15, ty = threadIdx.x >> 4;
    const float* Gb = Gp + (long)b * sCb;
    float* Ub = U + (long)b * sCb;
#pragma unroll
    for (int i = 0; i < 8; i++) {
        long base = (long)(m0 + ty * 8 + i) * ldc;
#pragma unroll
        for (int h = 0; h < 2; h++) {
            long off = base + n0 + h * 64 + tx * 4;
            float4 gv = *(const float4*)&Gb[off];
            float ga[4] = {gv.x, gv.y, gv.z, gv.w};
            float uo[4];
#pragma unroll
            for (int j = 0; j < 4; j++) {
                float g = ga[j];
                uo[j] = g * sigf(g) * acc[i][h * 4 + j];
            }
            *(float4*)&Ub[off] = make_float4(uo[0], uo[1], uo[2], uo[3]);
        }
    }
}

// ---------------------------------------------------------------------------
// NN GEMM + fused SwiGLU backprop epilogue: dh = V @ W1 (A ROW [C,Dout],
// B COL [Dout,DH]); then in-place  G <- dgba*lr0, HB <- dhbm*lr2, D <- hidden*lr1.
// ---------------------------------------------------------------------------
__global__ __launch_bounds__(256, 2) void k_nn_bprop(
    const float* __restrict__ V, long sVb,
    const float* __restrict__ W1,
    float* __restrict__ G, float* __restrict__ HB, float* __restrict__ D,
    const float* __restrict__ lr0, const float* __restrict__ lr1,
    const float* __restrict__ lr2, int row0) {
    const int b  = blockIdx.z;
    const int m0 = blockIdx.x * 128;
    const int n0 = blockIdx.y * 128;
    __shared__ float As[2][16][PA_ROW];
    __shared__ float Bs[2][16][PA_ROW];
    float acc[8][8] = {};
    g128_core<0, 1>(V + (long)b * sVb, DOUT,
                    W1 + (long)b * DOUT * DH, DH,
                    m0, n0, 0, DOUT / 16, acc, As, Bs);
    const int tx = threadIdx.x & 15, ty = threadIdx.x >> 4;
#pragma unroll
    for (int i = 0; i < 8; i++) {
        const int m = m0 + ty * 8 + i;
        const int li = b * LL + row0 + m;
        const float l0 = lr0[li], l1 = lr1[li], l2 = lr2[li];
        long base = ((long)b * CHK + m) * DH;
#pragma unroll
        for (int h = 0; h < 2; h++) {
            long off = base + n0 + h * 64 + tx * 4;
            float4 gv  = *(const float4*)&G [off];
            float4 hbv = *(const float4*)&HB[off];
            float ga[4] = {gv.x, gv.y, gv.z, gv.w};
            float ha[4] = {hbv.x, hbv.y, hbv.z, hbv.w};
            float go[4], ho[4], dv[4];
#pragma unroll
            for (int j = 0; j < 4; j++) {
                float g  = ga[j];
                float hb = ha[j];
                float dh = acc[i][h * 4 + j];
                float s  = sigf(g);
                float sg = s * g;
                dv[j] = sg * hb * l1;                             // hidden * lr1
                ho[j] = dh * sg * l2;                             // dhbm   * lr2
                go[j] = dh * hb * s * (1.f + g * (1.f - s)) * l0; // dgba   * lr0
            }
            *(float4*)&D [off] = make_float4(dv[0], dv[1], dv[2], dv[3]);
            *(float4*)&HB[off] = make_float4(ho[0], ho[1], ho[2], ho[3]);
            *(float4*)&G [off] = make_float4(go[0], go[1], go[2], go[3]);
        }
    }
}

// ---------------------------------------------------------------------------
// Split-K TN GEMM: P[s][b][m][n] = sum_{c in split s} A[c,m] * B[c,n].
// A COL [CHK, M], B COL [CHK, N].  blockIdx.z = b*SK + s.
// ---------------------------------------------------------------------------
__global__ __launch_bounds__(256, 2) void k_tn_sk(
    const float* __restrict__ A, long sAb, int lda,
    const float* __restrict__ B, long sBb, int ldb,
    float* __restrict__ P, int M, int N) {
    const int zz = blockIdx.z;
    const int b  = zz >> 2;      // SK = 4
    const int s  = zz & 3;
    const int m0 = blockIdx.x * 128;
    const int n0 = blockIdx.y * 128;
    __shared__ float As[2][16][PA_ROW];
    __shared__ float Bs[2][16][PA_ROW];
    float acc[8][8] = {};
    g128_core<1, 1>(A + (long)b * sAb, lda, B + (long)b * sBb, ldb,
                    m0, n0, s * (CHK / SK), (CHK / SK) / 16, acc, As, Bs);
    const int tx = threadIdx.x & 15, ty = threadIdx.x >> 4;
    float* Pb = P + ((long)s * BB + b) * ((long)M * N);
#pragma unroll
    for (int i = 0; i < 8; i++) {
        long base = (long)(m0 + ty * 8 + i) * N;
        *(float4*)&Pb[base + n0 + tx * 4] =
            make_float4(acc[i][0], acc[i][1], acc[i][2], acc[i][3]);
        *(float4*)&Pb[base + n0 + 64 + tx * 4] =
            make_float4(acc[i][4], acc[i][5], acc[i][6], acc[i][7]);
    }
}

// ---------------------------------------------------------------------------
// Old 128x64 core (kept for k_uw1: N=DOUT=256 keeps a full 256-block grid here).
// ---------------------------------------------------------------------------
__device__ __forceinline__ void gemm_core_nt(
    const float* __restrict__ Ab, int lda,
    const float* __restrict__ Bb, int ldb,
    int m0, int n0, int nkb,
    float acc[8][4],
    float (&As)[2][16][PA_ROW], float (&Bs)[2][16][PB_ROW]) {
    const int t  = threadIdx.x;
    const int tx = t & 15, ty = t >> 4;
    const int lr = t >> 2;
    const int lc = (t & 3) * 4;
    float4 ra0, ra1, rb;

#define LD_T(K0)                                                               \
    {                                                                          \
        ra0 = *(const float4*)&Ab[(long)(m0 + lr) * lda + (K0) + lc];          \
        ra1 = *(const float4*)&Ab[(long)(m0 + lr + 64) * lda + (K0) + lc];     \
        rb  = *(const float4*)&Bb[(long)(n0 + lr) * ldb + (K0) + lc];          \
    }
#define ST_T(BF)                                                               \
    {                                                                          \
        As[BF][lc + 0][lr] = ra0.x; As[BF][lc + 1][lr] = ra0.y;                \
        As[BF][lc + 2][lr] = ra0.z; As[BF][lc + 3][lr] = ra0.w;                \
        As[BF][lc + 0][lr + 64] = ra1.x; As[BF][lc + 1][lr + 64] = ra1.y;      \
        As[BF][lc + 2][lr + 64] = ra1.z; As[BF][lc + 3][lr + 64] = ra1.w;      \
        Bs[BF][lc + 0][lr] = rb.x; Bs[BF][lc + 1][lr] = rb.y;                  \
        Bs[BF][lc + 2][lr] = rb.z; Bs[BF][lc + 3][lr] = rb.w;                  \
    }

    LD_T(0);
    ST_T(0);
    __syncthreads();
    for (int kb = 0; kb < nkb; ++kb) {
        const int buf = kb & 1;
        if (kb + 1 < nkb) LD_T((kb + 1) * 16);
#pragma unroll
        for (int kk = 0; kk < 16; ++kk) {
            float4 x0 = *(const float4*)&As[buf][kk][ty * 8];
            float4 x1 = *(const float4*)&As[buf][kk][ty * 8 + 4];
            float4 bv = *(const float4*)&Bs[buf][kk][tx * 4];
            float xa[8] = {x0.x, x0.y, x0.z, x0.w, x1.x, x1.y, x1.z, x1.w};
            float wb[4] = {bv.x, bv.y, bv.z, bv.w};
#pragma unroll
            for (int i = 0; i < 8; i++)
#pragma unroll
                for (int j = 0; j < 4; j++) acc[i][j] += xa[i] * wb[j];
        }
        if (kb + 1 < nkb) {
            ST_T(buf ^ 1);
            __syncthreads();
        }
    }
#undef LD_T
#undef ST_T
}

// Out = U @ W1^T  (M=CHK, N=DOUT, K=DH). Out pre-offset to chunk.
__global__ __launch_bounds__(256, 3) void k_uw1(
    const float* __restrict__ U, const float* __restrict__ W1, float* __restrict__ O) {
    const int b  = blockIdx.z;
    const int m0 = blockIdx.x * 128;
    const int n0 = blockIdx.y * 64;
    __shared__ float As[2][16][PA_ROW];
    __shared__ float Bs[2][16][PB_ROW];
    float acc[8][4] = {};
    gemm_core_nt(U + (long)b * CHK * DH, DH,
                 W1 + (long)b * DOUT * DH, DH,
                 m0, n0, DH / 16, acc, As, Bs);
    const int tx = threadIdx.x & 15, ty = threadIdx.x >> 4;
    float* Ob = O + (long)b * LL * DOUT;
#pragma unroll
    for (int i = 0; i < 8; i++) {
        const int m = m0 + ty * 8 + i;
        *(float4*)&Ob[(long)m * DOUT + n0 + tx * 4] =
            make_float4(acc[i][0], acc[i][1], acc[i][2], acc[i][3]);
    }
}

// ---------------------------------------------------------------------------
// Host launcher
// ---------------------------------------------------------------------------
extern "C" void kernel_launch(void* const* d_in, const int* in_sizes, int n_in,
                              void* d_out, int out_size) {
    const float* w0  = (const float*)d_in[0];
    const float* w1  = (const float*)d_in[1];
    const float* w2  = (const float*)d_in[2];
    const float* q   = (const float*)d_in[3];
    const float* kk  = (const float*)d_in[4];
    const float* v   = (const float*)d_in[5];
    const float* lr0 = (const float*)d_in[6];
    const float* lr1 = (const float*)d_in[7];
    const float* lr2 = (const float*)d_in[8];
    float* out = (float*)d_out;

    float *w0c, *w0m, *w1c, *w1m, *w2c, *w2m, *w0n, *w1n, *w2n;
    float *G, *HB, *D, *U, *P0, *P2, *P1;
    cudaGetSymbolAddress((void**)&w0c, g_w0c);
    cudaGetSymbolAddress((void**)&w0m, g_w0m);
    cudaGetSymbolAddress((void**)&w1c, g_w1c);
    cudaGetSymbolAddress((void**)&w1m, g_w1m);
    cudaGetSymbolAddress((void**)&w2c, g_w2c);
    cudaGetSymbolAddress((void**)&w2m, g_w2m);
    cudaGetSymbolAddress((void**)&w0n, g_w0n);
    cudaGetSymbolAddress((void**)&w1n, g_w1n);
    cudaGetSymbolAddress((void**)&w2n, g_w2n);
    cudaGetSymbolAddress((void**)&G,   g_G);
    cudaGetSymbolAddress((void**)&HB,  g_HB);
    cudaGetSymbolAddress((void**)&D,   g_D);
    cudaGetSymbolAddress((void**)&U,   g_U);
    cudaGetSymbolAddress((void**)&P0,  g_P0);
    cudaGetSymbolAddress((void**)&P2,  g_P2);
    cudaGetSymbolAddress((void**)&P1,  g_P1);

    k_row_init<<<BB * DH, 256>>>(w0, w0c, w0m, w0n, DIN);
    k_row_init<<<BB * DOUT, 256>>>(w1, w1c, w1m, w1n, DH);
    k_row_init<<<BB * DH, 256>>>(w2, w2c, w2m, w2n, DIN);

    dim3 gNT(CHK / 128, DH / 128, BB);        // 8,4,8  (C x DH GEMMs)
    dim3 gU(CHK / 128, DOUT / 64, BB);        // 8,4,8  (old 128x64 core)
    dim3 gDw02(DH / 128, DIN / 128, BB * SK); // 4,2,32
    dim3 gDw1(DOUT / 128, DH / 128, BB * SK); // 2,4,32
    dim3 gRR02(BB * DH, 2, 1);
    dim3 gRR1(BB * DOUT, 1, 1);

    const long sX = (long)LL * DIN;     // q/k batch stride
    const long sV = (long)LL * DOUT;    // v batch stride
    const long sW02 = (long)DH * DIN;   // w0/w2 batch stride
    const long sT = (long)CHK * DH;     // G/HB/D/U batch stride

    for (int i = 0; i < NCHK; ++i) {
        long off = (long)i * CHK;
        // ---- apply current fast weights to queries (before update) ----
        // G = q @ w0^T ; U = silu(G) * (q @ w2^T) ; out = U @ w1^T
        k_nt<<<gNT, 256>>>(q + off * DIN, sX, DIN, w0c, sW02, DIN,
                           G, sT, DH, DIN / 16);
        k_nt_silu<<<gNT, 256>>>(q + off * DIN, sX, DIN, w2c, sW02, DIN,
                                G, U, sT, DH, DIN / 16);
        k_uw1<<<gU, 256>>>(U, w1c, out + off * DOUT);
        if (i == NCHK - 1) break;
        // ---- key-path forward: G = gate_before_act, HB = hidden_before_mul
        k_nt<<<gNT, 256>>>(kk + off * DIN, sX, DIN, w0c, sW02, DIN,
                           G, sT, DH, DIN / 16);
        k_nt<<<gNT, 256>>>(kk + off * DIN, sX, DIN, w2c, sW02, DIN,
                           HB, sT, DH, DIN / 16);
        // ---- dh = v @ w1, fused SwiGLU backprop + lr folding ----
        k_nn_bprop<<<gNT, 256>>>(v + off * DOUT, sV, w1c,
                                 G, HB, D, lr0, lr1, lr2, (int)off);
        // ---- split-K weight gradients (deterministic partials) ----
        k_tn_sk<<<gDw02, 256>>>(G,  sT, DH, kk + off * DIN, sX, DIN, P0, DH, DIN);
        k_tn_sk<<<gDw02, 256>>>(HB, sT, DH, kk + off * DIN, sX, DIN, P2, DH, DIN);
        k_tn_sk<<<gDw1, 256>>>(v + off * DOUT, sV, DOUT, D, sT, DH, P1, DOUT, DH);
        // ---- fused reduce + prenorm renorm ----
        k_rr<<<gRR02, 256>>>(P0, w0m, w0n, w0c, P2, w2m, w2n, w2c,
                             DIN, (long)BB * DH * DIN);
        k_rr<<<gRR1, 256>>>(P1, w1m, w1n, w1c, nullptr, nullptr, nullptr, nullptr,
                            DH, (long)BB * DOUT * DH);
    }
}

// round 12
// speedup vs baseline: 1.3582x; 1.0289x over previous
#include <cuda_runtime.h>
#include <cuda_bf16.h>
#include <cstdint>

// Problem shapes (fixed by dataset reference setup_inputs)
#define BB   8
#define LL   8192
#define DIN  256
#define DH   512
#define DOUT 256
#define CHK  1024
#define NCHK (LL / CHK)
#define SK   4            // split-K factor for dw GEMMs

// ---------------------------------------------------------------------------
// Scratch (device globals; no allocation allowed)
// ---------------------------------------------------------------------------
__device__ float g_w0c[BB * DH * DIN];
__device__ float g_w0m[BB * DH * DIN];
__device__ float g_w2c[BB * DH * DIN];
__device__ float g_w2m[BB * DH * DIN];
__device__ float g_w1c[BB * DOUT * DH];
__device__ float g_w1m[BB * DOUT * DH];
__device__ float g_w0n[BB * DH];
__device__ float g_w1n[BB * DOUT];
__device__ float g_w2n[BB * DH];
__device__ float g_G [BB * CHK * DH];   // gate_before_act   -> dgba*lr0
__device__ float g_HB[BB * CHK * DH];   // hidden_before_mul -> dhbm*lr2
__device__ float g_D [BB * CHK * DH];   // hidden*lr1 (for dw1)
__device__ float g_U [BB * CHK * DH];   // silu(g)*h for the q path
// split-K partial buffers
__device__ float g_P0[SK * BB * DH * DIN];
__device__ float g_P2[SK * BB * DH * DIN];
__device__ float g_P1[SK * BB * DOUT * DH];

__device__ __forceinline__ float sigf(float x) { return 1.f / (1.f + __expf(-x)); }

// Smem row paddings (row stride MUST stay multiple of 4 floats = 16 B so all
// float4 LDS/STS stay aligned; misalignment = err715).
#define PA_ROW 132   // 128-wide tiles
#define PB_ROW 68    // 64-wide tiles

// ---------------------------------------------------------------------------
// Row init: wn = ||w_row||, wc = wm = w
// ---------------------------------------------------------------------------
__global__ void k_row_init(const float* __restrict__ w, float* __restrict__ wc,
                           float* __restrict__ wm, float* __restrict__ wn, int len) {
    long row = blockIdx.x;
    const float* src = w + row * (long)len;
    float s = 0.f;
    for (int i = threadIdx.x; i < len; i += 256) {
        float x = src[i];
        s += x * x;
        wc[row * (long)len + i] = x;
        wm[row * (long)len + i] = x;
    }
    __shared__ float red[8];
    for (int o = 16; o; o >>= 1) s += __shfl_xor_sync(0xffffffffu, s, o);
    if ((threadIdx.x & 31) == 0) red[threadIdx.x >> 5] = s;
    __syncthreads();
    if (threadIdx.x == 0) {
        float tot = 0.f;
        for (int i = 0; i < 8; i++) tot += red[i];
        wn[row] = sqrtf(tot);
    }
}

// ---------------------------------------------------------------------------
// Fused split-K reduce + prenorm renorm.
// ---------------------------------------------------------------------------
__global__ void k_rr(const float* __restrict__ PA, float* __restrict__ wmA,
                     const float* __restrict__ wnA, float* __restrict__ wcA,
                     const float* __restrict__ PB, float* __restrict__ wmB,
                     const float* __restrict__ wnB, float* __restrict__ wcB,
                     int L, long tot) {
    const float* P  = blockIdx.y ? PB : PA;
    float*       wm = blockIdx.y ? wmB : wmA;
    const float* wn = blockIdx.y ? wnB : wnA;
    float*       wc = blockIdx.y ? wcB : wcA;
    long row = blockIdx.x;
    float vals[2];
    int cnt = 0;
    float s = 0.f;
    for (int i = threadIdx.x; i < L; i += 256) {
        long idx = row * (long)L + i;
        float v = wm[idx];
#pragma unroll
        for (int k = 0; k < SK; k++) v += P[(long)k * tot + idx];
        wm[idx] = v;
        vals[cnt++] = v;
        s += v * v;
    }
    __shared__ float red[8];
    __shared__ float scale;
    for (int o = 16; o; o >>= 1) s += __shfl_xor_sync(0xffffffffu, s, o);
    if ((threadIdx.x & 31) == 0) red[threadIdx.x >> 5] = s;
    __syncthreads();
    if (threadIdx.x == 0) {
        float tot2 = 0.f;
        for (int i = 0; i < 8; i++) tot2 += red[i];
        scale = wn[row] / (sqrtf(tot2) + 1e-5f);
    }
    __syncthreads();
    cnt = 0;
    for (int i = threadIdx.x; i < L; i += 256)
        wc[row * (long)L + i] = vals[cnt++] * scale;
}

// ---------------------------------------------------------------------------
// Dual NT GEMM, 64x64 tile, double buffered (occ 3): G = X@W0^T, H = X@W2^T.
// MODE 0: O0 = silu(G)*H (q path).  MODE 1: O0=G, O1=H (k path).
// Measured 42.3 TF/s @ occ 34%, conflict-free LDS.
// ---------------------------------------------------------------------------
template <int MODE>
__global__ __launch_bounds__(256, 3) void k_dual(
    const float* __restrict__ X,   // pre-offset to chunk; batch stride LL*DIN
    const float* __restrict__ W0, const float* __restrict__ W2,
    float* __restrict__ O0, float* __restrict__ O1) {
    const int b  = blockIdx.z;
    const int m0 = blockIdx.x * 64;
    const int n0 = blockIdx.y * 64;
    const float* Xb  = X  + (long)b * LL * DIN;
    const float* W0b = W0 + (long)b * DH * DIN;
    const float* W2b = W2 + (long)b * DH * DIN;

    __shared__ float As [2][16][PB_ROW];
    __shared__ float B0s[2][16][PB_ROW];
    __shared__ float B1s[2][16][PB_ROW];

    const int t  = threadIdx.x;
    const int tx = t & 15, ty = t >> 4;
    const int lr = t >> 2;         // 0..63
    const int lc = (t & 3) * 4;    // 0,4,8,12

    float a0[4][4] = {}, a1[4][4] = {};
    float4 ra, rb0, rb1;

    ra  = *(const float4*)&Xb [(long)(m0 + lr) * DIN + lc];
    rb0 = *(const float4*)&W0b[(long)(n0 + lr) * DIN + lc];
    rb1 = *(const float4*)&W2b[(long)(n0 + lr) * DIN + lc];
    As [0][lc + 0][lr] = ra.x;  As [0][lc + 1][lr] = ra.y;  As [0][lc + 2][lr] = ra.z;  As [0][lc + 3][lr] = ra.w;
    B0s[0][lc + 0][lr] = rb0.x; B0s[0][lc + 1][lr] = rb0.y; B0s[0][lc + 2][lr] = rb0.z; B0s[0][lc + 3][lr] = rb0.w;
    B1s[0][lc + 0][lr] = rb1.x; B1s[0][lc + 1][lr] = rb1.y; B1s[0][lc + 2][lr] = rb1.z; B1s[0][lc + 3][lr] = rb1.w;
    __syncthreads();

    const int NKB = DIN / 16;
    for (int kb = 0; kb < NKB; ++kb) {
        const int buf = kb & 1;
        if (kb + 1 < NKB) {
            const int k0 = (kb + 1) * 16;
            ra  = *(const float4*)&Xb [(long)(m0 + lr) * DIN + k0 + lc];
            rb0 = *(const float4*)&W0b[(long)(n0 + lr) * DIN + k0 + lc];
            rb1 = *(const float4*)&W2b[(long)(n0 + lr) * DIN + k0 + lc];
        }
#pragma unroll
        for (int kk = 0; kk < 16; ++kk) {
            float4 av = *(const float4*)&As [buf][kk][ty * 4];
            float4 b0 = *(const float4*)&B0s[buf][kk][tx * 4];
            float4 b1 = *(const float4*)&B1s[buf][kk][tx * 4];
            float xa[4] = {av.x, av.y, av.z, av.w};
            float wa[4] = {b0.x, b0.y, b0.z, b0.w};
            float wb[4] = {b1.x, b1.y, b1.z, b1.w};
#pragma unroll
            for (int i = 0; i < 4; i++)
#pragma unroll
                for (int j = 0; j < 4; j++) {
                    a0[i][j] += xa[i] * wa[j];
                    a1[i][j] += xa[i] * wb[j];
                }
        }
        if (kb + 1 < NKB) {
            const int nb = buf ^ 1;
            As [nb][lc + 0][lr] = ra.x;  As [nb][lc + 1][lr] = ra.y;  As [nb][lc + 2][lr] = ra.z;  As [nb][lc + 3][lr] = ra.w;
            B0s[nb][lc + 0][lr] = rb0.x; B0s[nb][lc + 1][lr] = rb0.y; B0s[nb][lc + 2][lr] = rb0.z; B0s[nb][lc + 3][lr] = rb0.w;
            B1s[nb][lc + 0][lr] = rb1.x; B1s[nb][lc + 1][lr] = rb1.y; B1s[nb][lc + 2][lr] = rb1.z; B1s[nb][lc + 3][lr] = rb1.w;
            __syncthreads();
        }
    }

#pragma unroll
    for (int i = 0; i < 4; i++) {
        const int m = m0 + ty * 4 + i;
        long rowb = ((long)b * CHK + m) * DH + n0 + tx * 4;
        if (MODE == 0) {
            float4 o;
            o.x = a0[i][0] * sigf(a0[i][0]) * a1[i][0];
            o.y = a0[i][1] * sigf(a0[i][1]) * a1[i][1];
            o.z = a0[i][2] * sigf(a0[i][2]) * a1[i][2];
            o.w = a0[i][3] * sigf(a0[i][3]) * a1[i][3];
            *(float4*)&O0[rowb] = o;
        } else {
            *(float4*)&O0[rowb] = make_float4(a0[i][0], a0[i][1], a0[i][2], a0[i][3]);
            *(float4*)&O1[rowb] = make_float4(a1[i][0], a1[i][1], a1[i][2], a1[i][3]);
        }
    }
}

// ---------------------------------------------------------------------------
// 128x64 double-buffered core, occ 3 (A ROW, B either ROW(NT) or COL(NN)).
// ---------------------------------------------------------------------------
template <int BL>
__device__ __forceinline__ void gemm_core(
    const float* __restrict__ Ab, int lda,
    const float* __restrict__ Bb, int ldb,
    int m0, int n0, int nkb,
    float acc[8][4],
    float (&As)[2][16][PA_ROW], float (&Bs)[2][16][PB_ROW]) {
    const int t  = threadIdx.x;
    const int tx = t & 15, ty = t >> 4;
    const int lr = t >> 2;          // 0..63
    const int lc = (t & 3) * 4;     // 0,4,8,12
    const int kq = t >> 4;          // 0..15
    const int q4 = (t & 15) * 4;    // 0..60
    float4 ra0, ra1, rb;

#define LD_T(K0)                                                               \
    {                                                                          \
        ra0 = *(const float4*)&Ab[(long)(m0 + lr) * lda + (K0) + lc];          \
        ra1 = *(const float4*)&Ab[(long)(m0 + lr + 64) * lda + (K0) + lc];     \
        if (BL == 0) {                                                         \
            rb = *(const float4*)&Bb[(long)(n0 + lr) * ldb + (K0) + lc];       \
        } else {                                                               \
            rb = *(const float4*)&Bb[(long)((K0) + kq) * ldb + n0 + q4];       \
        }                                                                      \
    }
#define ST_T(BF)                                                               \
    {                                                                          \
        As[BF][lc + 0][lr] = ra0.x; As[BF][lc + 1][lr] = ra0.y;                \
        As[BF][lc + 2][lr] = ra0.z; As[BF][lc + 3][lr] = ra0.w;                \
        As[BF][lc + 0][lr + 64] = ra1.x; As[BF][lc + 1][lr + 64] = ra1.y;      \
        As[BF][lc + 2][lr + 64] = ra1.z; As[BF][lc + 3][lr + 64] = ra1.w;      \
        if (BL == 0) {                                                         \
            Bs[BF][lc + 0][lr] = rb.x; Bs[BF][lc + 1][lr] = rb.y;              \
            Bs[BF][lc + 2][lr] = rb.z; Bs[BF][lc + 3][lr] = rb.w;              \
        } else {                                                               \
            *(float4*)&Bs[BF][kq][q4] = rb;                                    \
        }                                                                      \
    }

    LD_T(0);
    ST_T(0);
    __syncthreads();
    for (int kb = 0; kb < nkb; ++kb) {
        const int buf = kb & 1;
        if (kb + 1 < nkb) LD_T((kb + 1) * 16);
#pragma unroll
        for (int kk = 0; kk < 16; ++kk) {
            float4 x0 = *(const float4*)&As[buf][kk][ty * 8];
            float4 x1 = *(const float4*)&As[buf][kk][ty * 8 + 4];
            float4 bv = *(const float4*)&Bs[buf][kk][tx * 4];
            float xa[8] = {x0.x, x0.y, x0.z, x0.w, x1.x, x1.y, x1.z, x1.w};
            float wb[4] = {bv.x, bv.y, bv.z, bv.w};
#pragma unroll
            for (int i = 0; i < 8; i++)
#pragma unroll
                for (int j = 0; j < 4; j++) acc[i][j] += xa[i] * wb[j];
        }
        if (kb + 1 < nkb) {
            ST_T(buf ^ 1);
            __syncthreads();
        }
    }
#undef LD_T
#undef ST_T
}

// Out = U @ W1^T  (M=CHK, N=DOUT, K=DH). Out pre-offset to chunk.
__global__ __launch_bounds__(256, 3) void k_uw1(
    const float* __restrict__ U, const float* __restrict__ W1, float* __restrict__ O) {
    const int b  = blockIdx.z;
    const int m0 = blockIdx.x * 128;
    const int n0 = blockIdx.y * 64;
    __shared__ float As[2][16][PA_ROW];
    __shared__ float Bs[2][16][PB_ROW];
    float acc[8][4] = {};
    gemm_core<0>(U + (long)b * CHK * DH, DH,
                 W1 + (long)b * DOUT * DH, DH,
                 m0, n0, DH / 16, acc, As, Bs);
    const int tx = threadIdx.x & 15, ty = threadIdx.x >> 4;
    float* Ob = O + (long)b * LL * DOUT;
#pragma unroll
    for (int i = 0; i < 8; i++) {
        const int m = m0 + ty * 8 + i;
        *(float4*)&Ob[(long)m * DOUT + n0 + tx * 4] =
            make_float4(acc[i][0], acc[i][1], acc[i][2], acc[i][3]);
    }
}

// ---------------------------------------------------------------------------
// D = V @ W1 (M=CHK, N=DH, K=DOUT), fused SwiGLU backprop epilogue:
//   reads G, HB; writes G <- dgba*lr0, HB <- dhbm*lr2, D <- hidden*lr1.
// ---------------------------------------------------------------------------
__global__ __launch_bounds__(256, 3) void k_vw1bp(
    const float* __restrict__ V,   // pre-offset to chunk; batch stride LL*DOUT
    const float* __restrict__ W1,
    float* __restrict__ G, float* __restrict__ HB, float* __restrict__ D,
    const float* __restrict__ lr0, const float* __restrict__ lr1,
    const float* __restrict__ lr2, int row0) {
    const int b  = blockIdx.z;
    const int m0 = blockIdx.x * 128;
    const int n0 = blockIdx.y * 64;
    __shared__ float As[2][16][PA_ROW];
    __shared__ float Bs[2][16][PB_ROW];
    float acc[8][4] = {};
    gemm_core<1>(V + (long)b * LL * DOUT, DOUT,
                 W1 + (long)b * DOUT * DH, DH,
                 m0, n0, DOUT / 16, acc, As, Bs);
    const int tx = threadIdx.x & 15, ty = threadIdx.x >> 4;
#pragma unroll
    for (int i = 0; i < 8; i++) {
        const int m = m0 + ty * 8 + i;
        const int li = b * LL + row0 + m;
        const float l0 = lr0[li], l1 = lr1[li], l2 = lr2[li];
        long idx = ((long)b * CHK + m) * DH + n0 + tx * 4;
        float4 gv  = *(const float4*)&G [idx];
        float4 hbv = *(const float4*)&HB[idx];
        float ga[4] = {gv.x, gv.y, gv.z, gv.w};
        float ha[4] = {hbv.x, hbv.y, hbv.z, hbv.w};
        float go[4], ho[4], dv[4];
#pragma unroll
        for (int j = 0; j < 4; j++) {
            float g  = ga[j];
            float hb = ha[j];
            float dh = acc[i][j];
            float s  = sigf(g);
            float sg = s * g;
            dv[j] = sg * hb * l1;                             // hidden * lr1
            ho[j] = dh * sg * l2;                             // dhbm   * lr2
            go[j] = dh * hb * s * (1.f + g * (1.f - s)) * l0; // dgba   * lr0
        }
        *(float4*)&D [idx] = make_float4(dv[0], dv[1], dv[2], dv[3]);
        *(float4*)&HB[idx] = make_float4(ho[0], ho[1], ho[2], ho[3]);
        *(float4*)&G [idx] = make_float4(go[0], go[1], go[2], go[3]);
    }
}

// ---------------------------------------------------------------------------
// g128 core (128x128, 8x8/thread, occ 2) — kept ONLY for the split-K dw GEMMs,
// where it measured faster (z=32 grids keep the chip full regardless of occ).
// COL/COL only (direct copies).
// ---------------------------------------------------------------------------
__device__ __forceinline__ void g128_col(
    const float* __restrict__ Ab, int lda,
    const float* __restrict__ Bb, int ldb,
    int m0, int n0, int kStart, int nkb,
    float acc[8][8],
    float (&As)[2][16][PA_ROW], float (&Bs)[2][16][PA_ROW]) {
    const int t  = threadIdx.x;
    const int kr = t >> 4;          // 0..15
    const int cc = (t & 15) * 8;    // 0..120
    const int tx = t & 15, ty = t >> 4;
    float4 a0v, a1v, b0v, b1v;

#define C_LD(K0)                                                               \
    {                                                                          \
        a0v = *(const float4*)&Ab[(long)((K0) + kr) * lda + m0 + cc];          \
        a1v = *(const float4*)&Ab[(long)((K0) + kr) * lda + m0 + cc + 4];      \
        b0v = *(const float4*)&Bb[(long)((K0) + kr) * ldb + n0 + cc];          \
        b1v = *(const float4*)&Bb[(long)((K0) + kr) * ldb + n0 + cc + 4];      \
    }
#define C_ST(BF)                                                               \
    {                                                                          \
        *(float4*)&As[BF][kr][cc]     = a0v;                                   \
        *(float4*)&As[BF][kr][cc + 4] = a1v;                                   \
        *(float4*)&Bs[BF][kr][cc]     = b0v;                                   \
        *(float4*)&Bs[BF][kr][cc + 4] = b1v;                                   \
    }

    C_LD(kStart);
    C_ST(0);
    __syncthreads();
    for (int kb = 0; kb < nkb; ++kb) {
        const int buf = kb & 1;
        if (kb + 1 < nkb) C_LD(kStart + (kb + 1) * 16);
#pragma unroll
        for (int kk = 0; kk < 16; ++kk) {
            float4 xa0 = *(const float4*)&As[buf][kk][ty * 8];
            float4 xa1 = *(const float4*)&As[buf][kk][ty * 8 + 4];
            float4 xb0 = *(const float4*)&Bs[buf][kk][tx * 4];
            float4 xb1 = *(const float4*)&Bs[buf][kk][64 + tx * 4];
            float av[8] = {xa0.x, xa0.y, xa0.z, xa0.w, xa1.x, xa1.y, xa1.z, xa1.w};
            float bv[8] = {xb0.x, xb0.y, xb0.z, xb0.w, xb1.x, xb1.y, xb1.z, xb1.w};
#pragma unroll
            for (int i = 0; i < 8; i++)
#pragma unroll
                for (int j = 0; j < 8; j++) acc[i][j] += av[i] * bv[j];
        }
        if (kb + 1 < nkb) {
            C_ST(buf ^ 1);
            __syncthreads();
        }
    }
#undef C_LD
#undef C_ST
}

// Split-K TN GEMM: P[s][b][m][n] = sum_{c in split s} A[c,m]*B[c,n].
__global__ __launch_bounds__(256, 2) void k_tn_sk(
    const float* __restrict__ A, long sAb, int lda,
    const float* __restrict__ B, long sBb, int ldb,
    float* __restrict__ P, int M, int N) {
    const int zz = blockIdx.z;
    const int b  = zz >> 2;      // SK = 4
    const int s  = zz & 3;
    const int m0 = blockIdx.x * 128;
    const int n0 = blockIdx.y * 128;
    __shared__ float As[2][16][PA_ROW];
    __shared__ float Bs[2][16][PA_ROW];
    float acc[8][8] = {};
    g128_col(A + (long)b * sAb, lda, B + (long)b * sBb, ldb,
             m0, n0, s * (CHK / SK), (CHK / SK) / 16, acc, As, Bs);
    const int tx = threadIdx.x & 15, ty = threadIdx.x >> 4;
    float* Pb = P + ((long)s * BB + b) * ((long)M * N);
#pragma unroll
    for (int i = 0; i < 8; i++) {
        long base = (long)(m0 + ty * 8 + i) * N;
        *(float4*)&Pb[base + n0 + tx * 4] =
            make_float4(acc[i][0], acc[i][1], acc[i][2], acc[i][3]);
        *(float4*)&Pb[base + n0 + 64 + tx * 4] =
            make_float4(acc[i][4], acc[i][5], acc[i][6], acc[i][7]);
    }
}

// ---------------------------------------------------------------------------
// Host launcher
// ---------------------------------------------------------------------------
extern "C" void kernel_launch(void* const* d_in, const int* in_sizes, int n_in,
                              void* d_out, int out_size) {
    const float* w0  = (const float*)d_in[0];
    const float* w1  = (const float*)d_in[1];
    const float* w2  = (const float*)d_in[2];
    const float* q   = (const float*)d_in[3];
    const float* kk  = (const float*)d_in[4];
    const float* v   = (const float*)d_in[5];
    const float* lr0 = (const float*)d_in[6];
    const float* lr1 = (const float*)d_in[7];
    const float* lr2 = (const float*)d_in[8];
    float* out = (float*)d_out;

    float *w0c, *w0m, *w1c, *w1m, *w2c, *w2m, *w0n, *w1n, *w2n;
    float *G, *HB, *D, *U, *P0, *P2, *P1;
    cudaGetSymbolAddress((void**)&w0c, g_w0c);
    cudaGetSymbolAddress((void**)&w0m, g_w0m);
    cudaGetSymbolAddress((void**)&w1c, g_w1c);
    cudaGetSymbolAddress((void**)&w1m, g_w1m);
    cudaGetSymbolAddress((void**)&w2c, g_w2c);
    cudaGetSymbolAddress((void**)&w2m, g_w2m);
    cudaGetSymbolAddress((void**)&w0n, g_w0n);
    cudaGetSymbolAddress((void**)&w1n, g_w1n);
    cudaGetSymbolAddress((void**)&w2n, g_w2n);
    cudaGetSymbolAddress((void**)&G,   g_G);
    cudaGetSymbolAddress((void**)&HB,  g_HB);
    cudaGetSymbolAddress((void**)&D,   g_D);
    cudaGetSymbolAddress((void**)&U,   g_U);
    cudaGetSymbolAddress((void**)&P0,  g_P0);
    cudaGetSymbolAddress((void**)&P2,  g_P2);
    cudaGetSymbolAddress((void**)&P1,  g_P1);

    k_row_init<<<BB * DH, 256>>>(w0, w0c, w0m, w0n, DIN);
    k_row_init<<<BB * DOUT, 256>>>(w1, w1c, w1m, w1n, DH);
    k_row_init<<<BB * DH, 256>>>(w2, w2c, w2m, w2n, DIN);

    dim3 gDual(CHK / 64, DH / 64, BB);        // 16,8,8 (occ 3)
    dim3 gU(CHK / 128, DOUT / 64, BB);        // 8,4,8  (occ 3)
    dim3 gV(CHK / 128, DH / 64, BB);          // 8,8,8  (occ 3)
    dim3 gDw02(DH / 128, DIN / 128, BB * SK); // 4,2,32 (occ 2, chip-filling z)
    dim3 gDw1(DOUT / 128, DH / 128, BB * SK); // 2,4,32
    dim3 gRR02(BB * DH, 2, 1);
    dim3 gRR1(BB * DOUT, 1, 1);

    const long sX = (long)LL * DIN;     // q/k batch stride
    const long sV = (long)LL * DOUT;    // v batch stride
    const long sT = (long)CHK * DH;     // G/HB/D/U batch stride

    for (int i = 0; i < NCHK; ++i) {
        long off = (long)i * CHK;
        // ---- apply current fast weights to queries (before update) ----
        k_dual<0><<<gDual, 256>>>(q + off * DIN, w0c, w2c, U, nullptr);
        k_uw1<<<gU, 256>>>(U, w1c, out + off * DOUT);
        if (i == NCHK - 1) break;
        // ---- key-path forward: G = gate_before_act, HB = hidden_before_mul
        k_dual<1><<<gDual, 256>>>(kk + off * DIN, w0c, w2c, G, HB);
        // ---- dh = v @ w1, fused SwiGLU backprop + lr folding ----
        k_vw1bp<<<gV, 256>>>(v + off * DOUT, w1c, G, HB, D, lr0, lr1, lr2, (int)off);
        // ---- split-K weight gradients (deterministic partials) ----
        k_tn_sk<<<gDw02, 256>>>(G,  sT, DH, kk + off * DIN, sX, DIN, P0, DH, DIN);
        k_tn_sk<<<gDw02, 256>>>(HB, sT, DH, kk + off * DIN, sX, DIN, P2, DH, DIN);
        k_tn_sk<<<gDw1, 256>>>(v + off * DOUT, sV, DOUT, D, sT, DH, P1, DOUT, DH);
        // ---- fused reduce + prenorm renorm ----
        k_rr<<<gRR02, 256>>>(P0, w0m, w0n, w0c, P2, w2m, w2n, w2c,
                             DIN, (long)BB * DH * DIN);
        k_rr<<<gRR1, 256>>>(P1, w1m, w1n, w1c, nullptr, nullptr, nullptr, nullptr,
                            DH, (long)BB * DOUT * DH);
    }
}

// round 14
// speedup vs baseline: 1.3881x; 1.0220x over previous
#include <cuda_runtime.h>
#include <cuda_bf16.h>
#include <cstdint>

// Problem shapes (fixed by dataset reference setup_inputs)
#define BB   8
#define LL   8192
#define DIN  256
#define DH   512
#define DOUT 256
#define CHK  1024
#define NCHK (LL / CHK)
#define SK   4            // split-K factor for dw GEMMs

// ---------------------------------------------------------------------------
// Scratch (device globals; no allocation allowed)
// ---------------------------------------------------------------------------
__device__ float g_w0c[BB * DH * DIN];
__device__ float g_w0m[BB * DH * DIN];
__device__ float g_w2c[BB * DH * DIN];
__device__ float g_w2m[BB * DH * DIN];
__device__ float g_w1c[BB * DOUT * DH];
__device__ float g_w1m[BB * DOUT * DH];
__device__ float g_w0n[BB * DH];
__device__ float g_w1n[BB * DOUT];
__device__ float g_w2n[BB * DH];
__device__ float g_G [BB * CHK * DH];   // gate_before_act   -> dgba*lr0
__device__ float g_HB[BB * CHK * DH];   // hidden_before_mul -> dhbm*lr2
__device__ float g_D [BB * CHK * DH];   // hidden*lr1 (for dw1)
__device__ float g_U [BB * CHK * DH];   // silu(g)*h for the q path
// split-K partial buffers
__device__ float g_P0[SK * BB * DH * DIN];
__device__ float g_P2[SK * BB * DH * DIN];
__device__ float g_P1[SK * BB * DOUT * DH];

__device__ __forceinline__ float sigf(float x) { return 1.f / (1.f + __expf(-x)); }

// Smem row paddings (row stride MUST stay multiple of 4 floats = 16 B so all
// float4 LDS/STS stay aligned; misalignment = err715).
#define PA_ROW 132   // 128-wide tiles
#define PB_ROW 68    // 64-wide tiles

// ---------------------------------------------------------------------------
// Row init: wn = ||w_row||, wc = wm = w
// ---------------------------------------------------------------------------
__global__ void k_row_init(const float* __restrict__ w, float* __restrict__ wc,
                           float* __restrict__ wm, float* __restrict__ wn, int len) {
    long row = blockIdx.x;
    const float* src = w + row * (long)len;
    float s = 0.f;
    for (int i = threadIdx.x; i < len; i += 256) {
        float x = src[i];
        s += x * x;
        wc[row * (long)len + i] = x;
        wm[row * (long)len + i] = x;
    }
    __shared__ float red[8];
    for (int o = 16; o; o >>= 1) s += __shfl_xor_sync(0xffffffffu, s, o);
    if ((threadIdx.x & 31) == 0) red[threadIdx.x >> 5] = s;
    __syncthreads();
    if (threadIdx.x == 0) {
        float tot = 0.f;
        for (int i = 0; i < 8; i++) tot += red[i];
        wn[row] = sqrtf(tot);
    }
}

// ---------------------------------------------------------------------------
// Fused split-K reduce + prenorm renorm.
// ---------------------------------------------------------------------------
__global__ void k_rr(const float* __restrict__ PA, float* __restrict__ wmA,
                     const float* __restrict__ wnA, float* __restrict__ wcA,
                     const float* __restrict__ PB, float* __restrict__ wmB,
                     const float* __restrict__ wnB, float* __restrict__ wcB,
                     int L, long tot) {
    const float* P  = blockIdx.y ? PB : PA;
    float*       wm = blockIdx.y ? wmB : wmA;
    const float* wn = blockIdx.y ? wnB : wnA;
    float*       wc = blockIdx.y ? wcB : wcA;
    long row = blockIdx.x;
    float vals[2];
    int cnt = 0;
    float s = 0.f;
    for (int i = threadIdx.x; i < L; i += 256) {
        long idx = row * (long)L + i;
        float v = wm[idx];
#pragma unroll
        for (int k = 0; k < SK; k++) v += P[(long)k * tot + idx];
        wm[idx] = v;
        vals[cnt++] = v;
        s += v * v;
    }
    __shared__ float red[8];
    __shared__ float scale;
    for (int o = 16; o; o >>= 1) s += __shfl_xor_sync(0xffffffffu, s, o);
    if ((threadIdx.x & 31) == 0) red[threadIdx.x >> 5] = s;
    __syncthreads();
    if (threadIdx.x == 0) {
        float tot2 = 0.f;
        for (int i = 0; i < 8; i++) tot2 += red[i];
        scale = wn[row] / (sqrtf(tot2) + 1e-5f);
    }
    __syncthreads();
    cnt = 0;
    for (int i = threadIdx.x; i < L; i += 256)
        wc[row * (long)L + i] = vals[cnt++] * scale;
}

// ---------------------------------------------------------------------------
// Dual NT GEMM, 128x64 tile, 8x4/thread, double buffered (occ 2):
//   G = X@W0^T, H = X@W2^T.  Balanced pipes: 4 LDS.128 (16 cyc) vs 64 FFMA
//   (16 cyc) per k-step per warp.  MODE 0: O0 = silu(G)*H.  MODE 1: O0=G, O1=H.
// ---------------------------------------------------------------------------
template <int MODE>
__global__ __launch_bounds__(256, 2) void k_dual(
    const float* __restrict__ X,   // pre-offset to chunk; batch stride LL*DIN
    const float* __restrict__ W0, const float* __restrict__ W2,
    float* __restrict__ O0, float* __restrict__ O1) {
    const int b  = blockIdx.z;
    const int m0 = blockIdx.x * 128;
    const int n0 = blockIdx.y * 64;
    const float* Xb  = X  + (long)b * LL * DIN;
    const float* W0b = W0 + (long)b * DH * DIN;
    const float* W2b = W2 + (long)b * DH * DIN;

    __shared__ float As [2][16][PA_ROW];
    __shared__ float B0s[2][16][PB_ROW];
    __shared__ float B1s[2][16][PB_ROW];

    const int t  = threadIdx.x;
    const int tx = t & 15, ty = t >> 4;
    const int lr = t >> 2;         // 0..63
    const int lc = (t & 3) * 4;    // 0,4,8,12

    float a0[8][4] = {}, a1[8][4] = {};
    float4 ra0, ra1, rb0, rb1;

#define D_LD(K0)                                                                 \
    {                                                                            \
        ra0 = *(const float4*)&Xb [(long)(m0 + lr) * DIN + (K0) + lc];           \
        ra1 = *(const float4*)&Xb [(long)(m0 + lr + 64) * DIN + (K0) + lc];      \
        rb0 = *(const float4*)&W0b[(long)(n0 + lr) * DIN + (K0) + lc];           \
        rb1 = *(const float4*)&W2b[(long)(n0 + lr) * DIN + (K0) + lc];           \
    }
#define D_ST(BF)                                                                 \
    {                                                                            \
        As[BF][lc + 0][lr] = ra0.x; As[BF][lc + 1][lr] = ra0.y;                  \
        As[BF][lc + 2][lr] = ra0.z; As[BF][lc + 3][lr] = ra0.w;                  \
        As[BF][lc + 0][lr + 64] = ra1.x; As[BF][lc + 1][lr + 64] = ra1.y;        \
        As[BF][lc + 2][lr + 64] = ra1.z; As[BF][lc + 3][lr + 64] = ra1.w;        \
        B0s[BF][lc + 0][lr] = rb0.x; B0s[BF][lc + 1][lr] = rb0.y;                \
        B0s[BF][lc + 2][lr] = rb0.z; B0s[BF][lc + 3][lr] = rb0.w;                \
        B1s[BF][lc + 0][lr] = rb1.x; B1s[BF][lc + 1][lr] = rb1.y;                \
        B1s[BF][lc + 2][lr] = rb1.z; B1s[BF][lc + 3][lr] = rb1.w;                \
    }

    D_LD(0);
    D_ST(0);
    __syncthreads();

    const int NKB = DIN / 16;
    for (int kb = 0; kb < NKB; ++kb) {
        const int buf = kb & 1;
        if (kb + 1 < NKB) D_LD((kb + 1) * 16);
#pragma unroll
        for (int kk = 0; kk < 16; ++kk) {
            float4 x0 = *(const float4*)&As [buf][kk][ty * 8];
            float4 x1 = *(const float4*)&As [buf][kk][ty * 8 + 4];
            float4 b0 = *(const float4*)&B0s[buf][kk][tx * 4];
            float4 b1 = *(const float4*)&B1s[buf][kk][tx * 4];
            float xa[8] = {x0.x, x0.y, x0.z, x0.w, x1.x, x1.y, x1.z, x1.w};
            float wa[4] = {b0.x, b0.y, b0.z, b0.w};
            float wb[4] = {b1.x, b1.y, b1.z, b1.w};
#pragma unroll
            for (int i = 0; i < 8; i++)
#pragma unroll
                for (int j = 0; j < 4; j++) {
                    a0[i][j] += xa[i] * wa[j];
                    a1[i][j] += xa[i] * wb[j];
                }
        }
        if (kb + 1 < NKB) {
            D_ST(buf ^ 1);
            __syncthreads();
        }
    }
#undef D_LD
#undef D_ST

#pragma unroll
    for (int i = 0; i < 8; i++) {
        const int m = m0 + ty * 8 + i;
        long rowb = ((long)b * CHK + m) * DH + n0 + tx * 4;
        if (MODE == 0) {
            float4 o;
            o.x = a0[i][0] * sigf(a0[i][0]) * a1[i][0];
            o.y = a0[i][1] * sigf(a0[i][1]) * a1[i][1];
            o.z = a0[i][2] * sigf(a0[i][2]) * a1[i][2];
            o.w = a0[i][3] * sigf(a0[i][3]) * a1[i][3];
            *(float4*)&O0[rowb] = o;
        } else {
            *(float4*)&O0[rowb] = make_float4(a0[i][0], a0[i][1], a0[i][2], a0[i][3]);
            *(float4*)&O1[rowb] = make_float4(a1[i][0], a1[i][1], a1[i][2], a1[i][3]);
        }
    }
}

// ---------------------------------------------------------------------------
// 128x64 double-buffered core, occ 3 (A ROW, B either ROW(NT) or COL(NN)).
// ---------------------------------------------------------------------------
template <int BL>
__device__ __forceinline__ void gemm_core(
    const float* __restrict__ Ab, int lda,
    const float* __restrict__ Bb, int ldb,
    int m0, int n0, int nkb,
    float acc[8][4],
    float (&As)[2][16][PA_ROW], float (&Bs)[2][16][PB_ROW]) {
    const int t  = threadIdx.x;
    const int tx = t & 15, ty = t >> 4;
    const int lr = t >> 2;          // 0..63
    const int lc = (t & 3) * 4;     // 0,4,8,12
    const int kq = t >> 4;          // 0..15
    const int q4 = (t & 15) * 4;    // 0..60
    float4 ra0, ra1, rb;

#define LD_T(K0)                                                               \
    {                                                                          \
        ra0 = *(const float4*)&Ab[(long)(m0 + lr) * lda + (K0) + lc];          \
        ra1 = *(const float4*)&Ab[(long)(m0 + lr + 64) * lda + (K0) + lc];     \
        if (BL == 0) {                                                         \
            rb = *(const float4*)&Bb[(long)(n0 + lr) * ldb + (K0) + lc];       \
        } else {                                                               \
            rb = *(const float4*)&Bb[(long)((K0) + kq) * ldb + n0 + q4];       \
        }                                                                      \
    }
#define ST_T(BF)                                                               \
    {                                                                          \
        As[BF][lc + 0][lr] = ra0.x; As[BF][lc + 1][lr] = ra0.y;                \
        As[BF][lc + 2][lr] = ra0.z; As[BF][lc + 3][lr] = ra0.w;                \
        As[BF][lc + 0][lr + 64] = ra1.x; As[BF][lc + 1][lr + 64] = ra1.y;      \
        As[BF][lc + 2][lr + 64] = ra1.z; As[BF][lc + 3][lr + 64] = ra1.w;      \
        if (BL == 0) {                                                         \
            Bs[BF][lc + 0][lr] = rb.x; Bs[BF][lc + 1][lr] = rb.y;              \
            Bs[BF][lc + 2][lr] = rb.z; Bs[BF][lc + 3][lr] = rb.w;              \
        } else {                                                               \
            *(float4*)&Bs[BF][kq][q4] = rb;                                    \
        }                                                                      \
    }

    LD_T(0);
    ST_T(0);
    __syncthreads();
    for (int kb = 0; kb < nkb; ++kb) {
        const int buf = kb & 1;
        if (kb + 1 < nkb) LD_T((kb + 1) * 16);
#pragma unroll
        for (int kk = 0; kk < 16; ++kk) {
            float4 x0 = *(const float4*)&As[buf][kk][ty * 8];
            float4 x1 = *(const float4*)&As[buf][kk][ty * 8 + 4];
            float4 bv = *(const float4*)&Bs[buf][kk][tx * 4];
            float xa[8] = {x0.x, x0.y, x0.z, x0.w, x1.x, x1.y, x1.z, x1.w};
            float wb[4] = {bv.x, bv.y, bv.z, bv.w};
#pragma unroll
            for (int i = 0; i < 8; i++)
#pragma unroll
                for (int j = 0; j < 4; j++) acc[i][j] += xa[i] * wb[j];
        }
        if (kb + 1 < nkb) {
            ST_T(buf ^ 1);
            __syncthreads();
        }
    }
#undef LD_T
#undef ST_T
}

// Out = U @ W1^T  (M=CHK, N=DOUT, K=DH). Out pre-offset to chunk.
__global__ __launch_bounds__(256, 3) void k_uw1(
    const float* __restrict__ U, const float* __restrict__ W1, float* __restrict__ O) {
    const int b  = blockIdx.z;
    const int m0 = blockIdx.x * 128;
    const int n0 = blockIdx.y * 64;
    __shared__ float As[2][16][PA_ROW];
    __shared__ float Bs[2][16][PB_ROW];
    float acc[8][4] = {};
    gemm_core<0>(U + (long)b * CHK * DH, DH,
                 W1 + (long)b * DOUT * DH, DH,
                 m0, n0, DH / 16, acc, As, Bs);
    const int tx = threadIdx.x & 15, ty = threadIdx.x >> 4;
    float* Ob = O + (long)b * LL * DOUT;
#pragma unroll
    for (int i = 0; i < 8; i++) {
        const int m = m0 + ty * 8 + i;
        *(float4*)&Ob[(long)m * DOUT + n0 + tx * 4] =
            make_float4(acc[i][0], acc[i][1], acc[i][2], acc[i][3]);
    }
}

// ---------------------------------------------------------------------------
// D = V @ W1 (M=CHK, N=DH, K=DOUT), fused SwiGLU backprop epilogue:
//   reads G, HB; writes G <- dgba*lr0, HB <- dhbm*lr2, D <- hidden*lr1.
// ---------------------------------------------------------------------------
__global__ __launch_bounds__(256, 3) void k_vw1bp(
    const float* __restrict__ V,   // pre-offset to chunk; batch stride LL*DOUT
    const float* __restrict__ W1,
    float* __restrict__ G, float* __restrict__ HB, float* __restrict__ D,
    const float* __restrict__ lr0, const float* __restrict__ lr1,
    const float* __restrict__ lr2, int row0) {
    const int b  = blockIdx.z;
    const int m0 = blockIdx.x * 128;
    const int n0 = blockIdx.y * 64;
    __shared__ float As[2][16][PA_ROW];
    __shared__ float Bs[2][16][PB_ROW];
    float acc[8][4] = {};
    gemm_core<1>(V + (long)b * LL * DOUT, DOUT,
                 W1 + (long)b * DOUT * DH, DH,
                 m0, n0, DOUT / 16, acc, As, Bs);
    const int tx = threadIdx.x & 15, ty = threadIdx.x >> 4;
#pragma unroll
    for (int i = 0; i < 8; i++) {
        const int m = m0 + ty * 8 + i;
        const int li = b * LL + row0 + m;
        const float l0 = lr0[li], l1 = lr1[li], l2 = lr2[li];
        long idx = ((long)b * CHK + m) * DH + n0 + tx * 4;
        float4 gv  = *(const float4*)&G [idx];
        float4 hbv = *(const float4*)&HB[idx];
        float ga[4] = {gv.x, gv.y, gv.z, gv.w};
        float ha[4] = {hbv.x, hbv.y, hbv.z, hbv.w};
        float go[4], ho[4], dv[4];
#pragma unroll
        for (int j = 0; j < 4; j++) {
            float g  = ga[j];
            float hb = ha[j];
            float dh = acc[i][j];
            float s  = sigf(g);
            float sg = s * g;
            dv[j] = sg * hb * l1;                             // hidden * lr1
            ho[j] = dh * sg * l2;                             // dhbm   * lr2
            go[j] = dh * hb * s * (1.f + g * (1.f - s)) * l0; // dgba   * lr0
        }
        *(float4*)&D [idx] = make_float4(dv[0], dv[1], dv[2], dv[3]);
        *(float4*)&HB[idx] = make_float4(ho[0], ho[1], ho[2], ho[3]);
        *(float4*)&G [idx] = make_float4(go[0], go[1], go[2], go[3]);
    }
}

// ---------------------------------------------------------------------------
// g128 core (128x128, 8x8/thread, occ 2) — kept ONLY for the split-K dw GEMMs,
// where it measured faster (z=32 grids keep the chip full regardless of occ).
// COL/COL only (direct copies).
// ---------------------------------------------------------------------------
__device__ __forceinline__ void g128_col(
    const float* __restrict__ Ab, int lda,
    const float* __restrict__ Bb, int ldb,
    int m0, int n0, int kStart, int nkb,
    float acc[8][8],
    float (&As)[2][16][PA_ROW], float (&Bs)[2][16][PA_ROW]) {
    const int t  = threadIdx.x;
    const int kr = t >> 4;          // 0..15
    const int cc = (t & 15) * 8;    // 0..120
    const int tx = t & 15, ty = t >> 4;
    float4 a0v, a1v, b0v, b1v;

#define C_LD(K0)                                                               \
    {                                                                          \
        a0v = *(const float4*)&Ab[(long)((K0) + kr) * lda + m0 + cc];          \
        a1v = *(const float4*)&Ab[(long)((K0) + kr) * lda + m0 + cc + 4];      \
        b0v = *(const float4*)&Bb[(long)((K0) + kr) * ldb + n0 + cc];          \
        b1v = *(const float4*)&Bb[(long)((K0) + kr) * ldb + n0 + cc + 4];      \
    }
#define C_ST(BF)                                                               \
    {                                                                          \
        *(float4*)&As[BF][kr][cc]     = a0v;                                   \
        *(float4*)&As[BF][kr][cc + 4] = a1v;                                   \
        *(float4*)&Bs[BF][kr][cc]     = b0v;                                   \
        *(float4*)&Bs[BF][kr][cc + 4] = b1v;                                   \
    }

    C_LD(kStart);
    C_ST(0);
    __syncthreads();
    for (int kb = 0; kb < nkb; ++kb) {
        const int buf = kb & 1;
        if (kb + 1 < nkb) C_LD(kStart + (kb + 1) * 16);
#pragma unroll
        for (int kk = 0; kk < 16; ++kk) {
            float4 xa0 = *(const float4*)&As[buf][kk][ty * 8];
            float4 xa1 = *(const float4*)&As[buf][kk][ty * 8 + 4];
            float4 xb0 = *(const float4*)&Bs[buf][kk][tx * 4];
            float4 xb1 = *(const float4*)&Bs[buf][kk][64 + tx * 4];
            float av[8] = {xa0.x, xa0.y, xa0.z, xa0.w, xa1.x, xa1.y, xa1.z, xa1.w};
            float bv[8] = {xb0.x, xb0.y, xb0.z, xb0.w, xb1.x, xb1.y, xb1.z, xb1.w};
#pragma unroll
            for (int i = 0; i < 8; i++)
#pragma unroll
                for (int j = 0; j < 8; j++) acc[i][j] += av[i] * bv[j];
        }
        if (kb + 1 < nkb) {
            C_ST(buf ^ 1);
            __syncthreads();
        }
    }
#undef C_LD
#undef C_ST
}

// Split-K TN GEMM: P[s][b][m][n] = sum_{c in split s} A[c,m]*B[c,n].
__global__ __launch_bounds__(256, 2) void k_tn_sk(
    const float* __restrict__ A, long sAb, int lda,
    const float* __restrict__ B, long sBb, int ldb,
    float* __restrict__ P, int M, int N) {
    const int zz = blockIdx.z;
    const int b  = zz >> 2;      // SK = 4
    const int s  = zz & 3;
    const int m0 = blockIdx.x * 128;
    const int n0 = blockIdx.y * 128;
    __shared__ float As[2][16][PA_ROW];
    __shared__ float Bs[2][16][PA_ROW];
    float acc[8][8] = {};
    g128_col(A + (long)b * sAb, lda, B + (long)b * sBb, ldb,
             m0, n0, s * (CHK / SK), (CHK / SK) / 16, acc, As, Bs);
    const int tx = threadIdx.x & 15, ty = threadIdx.x >> 4;
    float* Pb = P + ((long)s * BB + b) * ((long)M * N);
#pragma unroll
    for (int i = 0; i < 8; i++) {
        long base = (long)(m0 + ty * 8 + i) * N;
        *(float4*)&Pb[base + n0 + tx * 4] =
            make_float4(acc[i][0], acc[i][1], acc[i][2], acc[i][3]);
        *(float4*)&Pb[base + n0 + 64 + tx * 4] =
            make_float4(acc[i][4], acc[i][5], acc[i][6], acc[i][7]);
    }
}

// ---------------------------------------------------------------------------
// Host launcher
// ---------------------------------------------------------------------------
extern "C" void kernel_launch(void* const* d_in, const int* in_sizes, int n_in,
                              void* d_out, int out_size) {
    const float* w0  = (const float*)d_in[0];
    const float* w1  = (const float*)d_in[1];
    const float* w2  = (const float*)d_in[2];
    const float* q   = (const float*)d_in[3];
    const float* kk  = (const float*)d_in[4];
    const float* v   = (const float*)d_in[5];
    const float* lr0 = (const float*)d_in[6];
    const float* lr1 = (const float*)d_in[7];
    const float* lr2 = (const float*)d_in[8];
    float* out = (float*)d_out;

    float *w0c, *w0m, *w1c, *w1m, *w2c, *w2m, *w0n, *w1n, *w2n;
    float *G, *HB, *D, *U, *P0, *P2, *P1;
    cudaGetSymbolAddress((void**)&w0c, g_w0c);
    cudaGetSymbolAddress((void**)&w0m, g_w0m);
    cudaGetSymbolAddress((void**)&w1c, g_w1c);
    cudaGetSymbolAddress((void**)&w1m, g_w1m);
    cudaGetSymbolAddress((void**)&w2c, g_w2c);
    cudaGetSymbolAddress((void**)&w2m, g_w2m);
    cudaGetSymbolAddress((void**)&w0n, g_w0n);
    cudaGetSymbolAddress((void**)&w1n, g_w1n);
    cudaGetSymbolAddress((void**)&w2n, g_w2n);
    cudaGetSymbolAddress((void**)&G,   g_G);
    cudaGetSymbolAddress((void**)&HB,  g_HB);
    cudaGetSymbolAddress((void**)&D,   g_D);
    cudaGetSymbolAddress((void**)&U,   g_U);
    cudaGetSymbolAddress((void**)&P0,  g_P0);
    cudaGetSymbolAddress((void**)&P2,  g_P2);
    cudaGetSymbolAddress((void**)&P1,  g_P1);

    k_row_init<<<BB * DH, 256>>>(w0, w0c, w0m, w0n, DIN);
    k_row_init<<<BB * DOUT, 256>>>(w1, w1c, w1m, w1n, DH);
    k_row_init<<<BB * DH, 256>>>(w2, w2c, w2m, w2n, DIN);

    dim3 gDual(CHK / 128, DH / 64, BB);       // 8,8,8 (128x64 dual, occ 2)
    dim3 gU(CHK / 128, DOUT / 64, BB);        // 8,4,8  (occ 3)
    dim3 gV(CHK / 128, DH / 64, BB);          // 8,8,8  (occ 3)
    dim3 gDw02(DH / 128, DIN / 128, BB * SK); // 4,2,32 (occ 2, chip-filling z)
    dim3 gDw1(DOUT / 128, DH / 128, BB * SK); // 2,4,32
    dim3 gRR02(BB * DH, 2, 1);
    dim3 gRR1(BB * DOUT, 1, 1);

    const long sX = (long)LL * DIN;     // q/k batch stride
    const long sV = (long)LL * DOUT;    // v batch stride
    const long sT = (long)CHK * DH;     // G/HB/D/U batch stride

    for (int i = 0; i < NCHK; ++i) {
        long off = (long)i * CHK;
        // ---- apply current fast weights to queries (before update) ----
        k_dual<0><<<gDual, 256>>>(q + off * DIN, w0c, w2c, U, nullptr);
        k_uw1<<<gU, 256>>>(U, w1c, out + off * DOUT);
        if (i == NCHK - 1) break;
        // ---- key-path forward: G = gate_before_act, HB = hidden_before_mul
        k_dual<1><<<gDual, 256>>>(kk + off * DIN, w0c, w2c, G, HB);
        // ---- dh = v @ w1, fused SwiGLU backprop + lr folding ----
        k_vw1bp<<<gV, 256>>>(v + off * DOUT, w1c, G, HB, D, lr0, lr1, lr2, (int)off);
        // ---- split-K weight gradients (deterministic partials) ----
        k_tn_sk<<<gDw02, 256>>>(G,  sT, DH, kk + off * DIN, sX, DIN, P0, DH, DIN);
        k_tn_sk<<<gDw02, 256>>>(HB, sT, DH, kk + off * DIN, sX, DIN, P2, DH, DIN);
        k_tn_sk<<<gDw1, 256>>>(v + off * DOUT, sV, DOUT, D, sT, DH, P1, DOUT, DH);
        // ---- fused reduce + prenorm renorm ----
        k_rr<<<gRR02, 256>>>(P0, w0m, w0n, w0c, P2, w2m, w2n, w2c,
                             DIN, (long)BB * DH * DIN);
        k_rr<<<gRR1, 256>>>(P1, w1m, w1n, w1c, nullptr, nullptr, nullptr, nullptr,
                            DH, (long)BB * DOUT * DH);
    }
}